// round 6
// baseline (speedup 1.0000x reference)
#include <cuda_runtime.h>
#include <cstdint>

#define QLEN  1024
#define MLEN  1024
#define KLENN 2048
#define BATCH 4
#define NH    16
#define DH    64
#define DM    1024

// Scratch: no allocation allowed -> device globals (~104 MB).
__device__ float g_Q[BATCH*NH*QLEN*DH];
__device__ float g_K[BATCH*NH*KLENN*DH];
__device__ float g_V[BATCH*NH*KLENN*DH];
__device__ float g_R[NH*KLENN*DH];
__device__ float g_AV[QLEN*BATCH*DM];
__device__ float g_O[QLEN*BATCH*DM];

__device__ __forceinline__ float ex2(float x) {
    float y; asm("ex2.approx.ftz.f32 %0, %1;" : "=f"(y) : "f"(x)); return y;
}

// ---------------------------------------------------------------------------
// tf32 helpers: Markidis split (hi = tf32(x), lo = tf32(x - hi))
// ---------------------------------------------------------------------------
__device__ __forceinline__ void tf32_split(float x, float& hi, float& lo) {
    uint32_t b;
    asm("cvt.rna.tf32.f32 %0, %1;" : "=r"(b) : "f"(x));
    hi = __uint_as_float(b);
    float r = x - hi;
    uint32_t b2;
    asm("cvt.rna.tf32.f32 %0, %1;" : "=r"(b2) : "f"(r));
    lo = __uint_as_float(b2);
}

__device__ __forceinline__ void mma8(float c[4],
    uint32_t a0, uint32_t a1, uint32_t a2, uint32_t a3,
    uint32_t b0, uint32_t b1)
{
    asm volatile(
        "mma.sync.aligned.m16n8k8.row.col.f32.tf32.tf32.f32 "
        "{%0,%1,%2,%3}, {%4,%5,%6,%7}, {%8,%9}, {%0,%1,%2,%3};"
        : "+f"(c[0]), "+f"(c[1]), "+f"(c[2]), "+f"(c[3])
        : "r"(a0), "r"(a1), "r"(a2), "r"(a3), "r"(b0), "r"(b1));
}

// ---------------------------------------------------------------------------
// 128x128x(k16) 3xTF32 GEMM mainloop.
// Warp grid 2x4 (warp tile 64x32). C[mt][nt][4] per thread (64 floats).
// As*/Bs* are [16][AP] smem planes (hi/lo), transposed A (k-major rows).
// ---------------------------------------------------------------------------
#define AP 132

__device__ __forceinline__ void gemm_tf32(
    const float* __restrict__ Arow, const float* __restrict__ B, int ldb, int n0,
    float (&C)[4][4][4],
    float (*AsB)[AP], float (*AsS)[AP], float (*BsB)[AP], float (*BsS)[AP],
    int t)
{
    const int ar = t>>1, ac = (t&1)<<3, br = t>>5, bc = (t&31)<<2;
    const int lane = t&31, w = t>>5;
    const int wm = w>>2, wn = w&3;
    const int tig = lane&3, grp = lane>>2;

    for (int kt = 0; kt < DM; kt += 16) {
        float a[8];
        #pragma unroll
        for (int i = 0; i < 8; i++) a[i] = Arow[kt + ac + i];
        float4 bv0 = *(const float4*)(B + (size_t)(kt + br) * ldb + n0 + bc);
        float4 bv1 = *(const float4*)(B + (size_t)(kt + br + 8) * ldb + n0 + bc);
        __syncthreads();
        #pragma unroll
        for (int i = 0; i < 8; i++) {
            float h, l; tf32_split(a[i], h, l);
            AsB[ac+i][ar] = h; AsS[ac+i][ar] = l;
        }
        {
            float e[4] = {bv0.x, bv0.y, bv0.z, bv0.w};
            float h[4], l[4];
            #pragma unroll
            for (int i = 0; i < 4; i++) tf32_split(e[i], h[i], l[i]);
            *(float4*)&BsB[br][bc] = make_float4(h[0],h[1],h[2],h[3]);
            *(float4*)&BsS[br][bc] = make_float4(l[0],l[1],l[2],l[3]);
            float e2[4] = {bv1.x, bv1.y, bv1.z, bv1.w};
            #pragma unroll
            for (int i = 0; i < 4; i++) tf32_split(e2[i], h[i], l[i]);
            *(float4*)&BsB[br+8][bc] = make_float4(h[0],h[1],h[2],h[3]);
            *(float4*)&BsS[br+8][bc] = make_float4(l[0],l[1],l[2],l[3]);
        }
        __syncthreads();

        #pragma unroll
        for (int k8 = 0; k8 < 16; k8 += 8) {
            uint32_t aB[4][4], aS[4][4], bB[4][2], bS[4][2];
            #pragma unroll
            for (int mt = 0; mt < 4; mt++) {
                int m0 = wm*64 + mt*16 + grp;
                aB[mt][0] = __float_as_uint(AsB[k8+tig  ][m0  ]);
                aB[mt][1] = __float_as_uint(AsB[k8+tig  ][m0+8]);
                aB[mt][2] = __float_as_uint(AsB[k8+tig+4][m0  ]);
                aB[mt][3] = __float_as_uint(AsB[k8+tig+4][m0+8]);
                aS[mt][0] = __float_as_uint(AsS[k8+tig  ][m0  ]);
                aS[mt][1] = __float_as_uint(AsS[k8+tig  ][m0+8]);
                aS[mt][2] = __float_as_uint(AsS[k8+tig+4][m0  ]);
                aS[mt][3] = __float_as_uint(AsS[k8+tig+4][m0+8]);
            }
            #pragma unroll
            for (int nt = 0; nt < 4; nt++) {
                int nc = wn*32 + nt*8 + grp;
                bB[nt][0] = __float_as_uint(BsB[k8+tig  ][nc]);
                bB[nt][1] = __float_as_uint(BsB[k8+tig+4][nc]);
                bS[nt][0] = __float_as_uint(BsS[k8+tig  ][nc]);
                bS[nt][1] = __float_as_uint(BsS[k8+tig+4][nc]);
            }
            #pragma unroll
            for (int mt = 0; mt < 4; mt++) {
                #pragma unroll
                for (int nt = 0; nt < 4; nt++) {
                    mma8(C[mt][nt], aB[mt][0],aB[mt][1],aB[mt][2],aB[mt][3], bB[nt][0],bB[nt][1]);
                    mma8(C[mt][nt], aB[mt][0],aB[mt][1],aB[mt][2],aB[mt][3], bS[nt][0],bS[nt][1]);
                    mma8(C[mt][nt], aS[mt][0],aS[mt][1],aS[mt][2],aS[mt][3], bB[nt][0],bB[nt][1]);
                }
            }
        }
    }
}

// GEMM 1: [mems;content] @ W_qkv, scatter -> g_Q/g_K/g_V.
__global__ __launch_bounds__(256, 1)
void k_qkv(const float* __restrict__ content, const float* __restrict__ mems,
           const float* __restrict__ W)
{
    __shared__ float AsB[16][AP], AsS[16][AP], BsB[16][AP], BsS[16][AP];
    const int t = threadIdx.x, n0 = blockIdx.x<<7, m0 = blockIdx.y<<7;
    const int lane = t&31, w = t>>5, wm = w>>2, wn = w&3;
    const int tig = lane&3, grp = lane>>2;
    const int ar = t>>1;
    const int mA = m0 + ar;
    const float* Arow = (mA < MLEN*BATCH) ? (mems + (size_t)mA*DM)
                                          : (content + (size_t)(mA - MLEN*BATCH)*DM);
    float C[4][4][4];
    #pragma unroll
    for (int i = 0; i < 4; i++) {
        #pragma unroll
        for (int j = 0; j < 4; j++) {
            #pragma unroll
            for (int k = 0; k < 4; k++) C[i][j][k] = 0.f;
        }
    }
    gemm_tf32(Arow, W, 3072, n0, C, AsB, AsS, BsB, BsS, t);

    #pragma unroll
    for (int mt = 0; mt < 4; mt++) {
        #pragma unroll
        for (int h = 0; h < 2; h++) {
            int m = m0 + wm*64 + mt*16 + grp + 8*h;
            int row = m >> 2, bb = m & 3;
            #pragma unroll
            for (int nt = 0; nt < 4; nt++) {
                int col = n0 + wn*32 + nt*8 + 2*tig;
                int sec = col >> 10, nn = (col>>6)&15, dd = col & 63;
                float2 v = make_float2(C[mt][nt][2*h], C[mt][nt][2*h+1]);
                if (sec == 0) {
                    if (row >= MLEN)
                        *(float2*)&g_Q[(((size_t)bb*NH+nn)*QLEN + (row-MLEN))*DH + dd] = v;
                } else if (sec == 1) {
                    *(float2*)&g_K[(((size_t)bb*NH+nn)*KLENN + row)*DH + dd] = v;
                } else {
                    *(float2*)&g_V[(((size_t)bb*NH+nn)*KLENN + row)*DH + dd] = v;
                }
            }
        }
    }
}

// GEMM 2: rel_pos @ W_r -> g_R[n][m][d]
__global__ __launch_bounds__(256, 1)
void k_rproj(const float* __restrict__ relpos, const float* __restrict__ W)
{
    __shared__ float AsB[16][AP], AsS[16][AP], BsB[16][AP], BsS[16][AP];
    const int t = threadIdx.x, n0 = blockIdx.x<<7, m0 = blockIdx.y<<7;
    const int lane = t&31, w = t>>5, wm = w>>2, wn = w&3;
    const int tig = lane&3, grp = lane>>2;
    const float* Arow = relpos + (size_t)(m0 + (t>>1))*DM;
    float C[4][4][4];
    #pragma unroll
    for (int i = 0; i < 4; i++) {
        #pragma unroll
        for (int j = 0; j < 4; j++) {
            #pragma unroll
            for (int k = 0; k < 4; k++) C[i][j][k] = 0.f;
        }
    }
    gemm_tf32(Arow, W, DM, n0, C, AsB, AsS, BsB, BsS, t);

    #pragma unroll
    for (int mt = 0; mt < 4; mt++) {
        #pragma unroll
        for (int h = 0; h < 2; h++) {
            int m = m0 + wm*64 + mt*16 + grp + 8*h;
            #pragma unroll
            for (int nt = 0; nt < 4; nt++) {
                int col = n0 + wn*32 + nt*8 + 2*tig;
                int nn = col >> 6, dd = col & 63;
                float2 v = make_float2(C[mt][nt][2*h], C[mt][nt][2*h+1]);
                *(float2*)&g_R[((size_t)nn*KLENN + m)*DH + dd] = v;
            }
        }
    }
}

// GEMM 3: g_AV @ W_o + content -> g_O
__global__ __launch_bounds__(256, 1)
void k_out(const float* __restrict__ content, const float* __restrict__ W)
{
    __shared__ float AsB[16][AP], AsS[16][AP], BsB[16][AP], BsS[16][AP];
    const int t = threadIdx.x, n0 = blockIdx.x<<7, m0 = blockIdx.y<<7;
    const int lane = t&31, w = t>>5, wm = w>>2, wn = w&3;
    const int tig = lane&3, grp = lane>>2;
    const float* Arow = g_AV + (size_t)(m0 + (t>>1))*DM;
    float C[4][4][4];
    #pragma unroll
    for (int i = 0; i < 4; i++) {
        #pragma unroll
        for (int j = 0; j < 4; j++) {
            #pragma unroll
            for (int k = 0; k < 4; k++) C[i][j][k] = 0.f;
        }
    }
    gemm_tf32(Arow, W, DM, n0, C, AsB, AsS, BsB, BsS, t);

    #pragma unroll
    for (int mt = 0; mt < 4; mt++) {
        #pragma unroll
        for (int h = 0; h < 2; h++) {
            size_t m = m0 + wm*64 + mt*16 + grp + 8*h;
            #pragma unroll
            for (int nt = 0; nt < 4; nt++) {
                int col = n0 + wn*32 + nt*8 + 2*tig;
                float2 c4 = *(const float2*)(content + m*DM + col);
                float2 v = make_float2(C[mt][nt][2*h] + c4.x, C[mt][nt][2*h+1] + c4.y);
                *(float2*)&g_O[m*DM + col] = v;
            }
        }
    }
}

// ---------------------------------------------------------------------------
// Fused flash attention with Transformer-XL rel-shift (fp32, unchanged).
// ---------------------------------------------------------------------------
#define SMF_QA 0
#define SMF_QB 4096
#define SMF_KT 8192
#define SMF_VT 12288
#define SMF_RT 16384
#define SMF_PS 24576
#define SMEM_ATTN ((24576 + 64*68) * 4)

__global__ __launch_bounds__(256)
void k_attn(const float* __restrict__ rwb, const float* __restrict__ rrb)
{
    extern __shared__ float smf[];
    float* qaT = smf + SMF_QA;
    float* qbT = smf + SMF_QB;
    float* ktT = smf + SMF_KT;
    float* vt  = smf + SMF_VT;
    float* rtT = smf + SMF_RT;
    float* ps  = smf + SMF_PS;

    const int t = threadIdx.x, lane = t&31, w = t>>5, tx = t&15, ty = t>>4;
    const int i0 = blockIdx.x<<6, n = blockIdx.y, b = blockIdx.z;

    const float* Qb = g_Q + (size_t)(b*NH+n)*QLEN*DH;
    const float* Kb = g_K + (size_t)(b*NH+n)*KLENN*DH;
    const float* Vb = g_V + (size_t)(b*NH+n)*KLENN*DH;
    const float* Rb = g_R + (size_t)n*KLENN*DH;

    {
        int qrow = lane + ((w>>2)<<5);
        int d0 = (w&3)<<4;
        const float* qp = Qb + (size_t)(i0+qrow)*DH + d0;
        #pragma unroll
        for (int u = 0; u < 4; u++) {
            float4 v = *(const float4*)(qp + 4*u);
            int d = d0 + 4*u;
            qaT[(d+0)*64+qrow]=v.x+rwb[n*DH+d+0]; qbT[(d+0)*64+qrow]=v.x+rrb[n*DH+d+0];
            qaT[(d+1)*64+qrow]=v.y+rwb[n*DH+d+1]; qbT[(d+1)*64+qrow]=v.y+rrb[n*DH+d+1];
            qaT[(d+2)*64+qrow]=v.z+rwb[n*DH+d+2]; qbT[(d+2)*64+qrow]=v.z+rrb[n*DH+d+2];
            qaT[(d+3)*64+qrow]=v.w+rwb[n*DH+d+3]; qbT[(d+3)*64+qrow]=v.w+rrb[n*DH+d+3];
        }
    }

    float mrow[4], lrow[4], o[4][4];
    #pragma unroll
    for (int a = 0; a < 4; a++) {
        mrow[a] = -1e30f; lrow[a] = 0.f;
        #pragma unroll
        for (int c = 0; c < 4; c++) o[a][c] = 0.f;
    }

    const float fscale = 0.18033688011112042f;
    const int ntiles = (i0>>6) + 17;
    const int rb4 = ((tx - ty)<<2) + 60;

    for (int tile = 0; tile < ntiles; tile++) {
        const int j0 = tile<<6;
        __syncthreads();
        {
            int jc = lane + ((w>>2)<<5); int d0 = (w&3)<<4;
            const float* kp = Kb + (size_t)(j0+jc)*DH + d0;
            #pragma unroll
            for (int u = 0; u < 4; u++) {
                float4 v = *(const float4*)(kp + 4*u); int d = d0 + 4*u;
                ktT[(d+0)*64+jc]=v.x; ktT[(d+1)*64+jc]=v.y;
                ktT[(d+2)*64+jc]=v.z; ktT[(d+3)*64+jc]=v.w;
            }
        }
        {
            int jc = t>>2; int d0 = (t&3)<<4;
            const float* vp = Vb + (size_t)(j0+jc)*DH + d0;
            #pragma unroll
            for (int u = 0; u < 4; u++)
                *(float4*)&vt[jc*64 + d0 + 4*u] = *(const float4*)(vp + 4*u);
        }
        {
            int rr = lane + ((w>>1)<<5); int d0 = (w&1)<<5;
            int mg = j0 + 960 - i0 + rr;
            #pragma unroll
            for (int u = 0; u < 8; u++) {
                int d = d0 + 4*u;
                float4 v = make_float4(0.f,0.f,0.f,0.f);
                if (mg < KLENN) v = *(const float4*)(Rb + (size_t)mg*DH + d);
                rtT[(d+0)*128+rr]=v.x; rtT[(d+1)*128+rr]=v.y;
                rtT[(d+2)*128+rr]=v.z; rtT[(d+3)*128+rr]=v.w;
            }
        }
        __syncthreads();

        float acc[4][4];
        #pragma unroll
        for (int a = 0; a < 4; a++) {
            #pragma unroll
            for (int c = 0; c < 4; c++) acc[a][c] = 0.f;
        }
        #pragma unroll 8
        for (int d = 0; d < 64; d++) {
            float4 qa4 = *(const float4*)&qaT[d*64 + (ty<<2)];
            float4 qb4 = *(const float4*)&qbT[d*64 + (ty<<2)];
            float4 kk4 = *(const float4*)&ktT[d*64 + (tx<<2)];
            float4 r04 = *(const float4*)&rtT[d*128 + rb4];
            float4 r14 = *(const float4*)&rtT[d*128 + rb4 + 4];
            float qaa[4]={qa4.x,qa4.y,qa4.z,qa4.w};
            float qbb[4]={qb4.x,qb4.y,qb4.z,qb4.w};
            float kkk[4]={kk4.x,kk4.y,kk4.z,kk4.w};
            float rr7[7]={r04.x,r04.y,r04.z,r04.w,r14.x,r14.y,r14.z};
            #pragma unroll
            for (int a = 0; a < 4; a++) {
                #pragma unroll
                for (int c = 0; c < 4; c++)
                    acc[a][c] += qaa[a]*kkk[c] + qbb[a]*rr7[c-a+3];
            }
        }

        #pragma unroll
        for (int a = 0; a < 4; a++) {
            const int iq = i0 + (ty<<2) + a;
            float s[4];
            #pragma unroll
            for (int c = 0; c < 4; c++) {
                int jk = j0 + (tx<<2) + c;
                s[c] = (jk > iq + MLEN) ? -1e30f : acc[a][c]*fscale;
            }
            float tm = fmaxf(fmaxf(s[0],s[1]), fmaxf(s[2],s[3]));
            tm = fmaxf(tm, __shfl_xor_sync(0xffffffffu, tm, 8));
            tm = fmaxf(tm, __shfl_xor_sync(0xffffffffu, tm, 4));
            tm = fmaxf(tm, __shfl_xor_sync(0xffffffffu, tm, 2));
            tm = fmaxf(tm, __shfl_xor_sync(0xffffffffu, tm, 1));
            float mn = fmaxf(mrow[a], tm);
            float cf = ex2(mrow[a] - mn);
            mrow[a] = mn;
            float p0=ex2(s[0]-mn), p1=ex2(s[1]-mn), p2=ex2(s[2]-mn), p3=ex2(s[3]-mn);
            lrow[a] = lrow[a]*cf + (p0+p1+p2+p3);
            #pragma unroll
            for (int c = 0; c < 4; c++) o[a][c] *= cf;
            *(float4*)&ps[((ty<<2)+a)*68 + (tx<<2)] = make_float4(p0,p1,p2,p3);
        }
        __syncthreads();

        #pragma unroll 4
        for (int j = 0; j < 64; j++) {
            float4 v4 = *(const float4*)&vt[j*64 + (tx<<2)];
            #pragma unroll
            for (int a = 0; a < 4; a++) {
                float pa = ps[((ty<<2)+a)*68 + j];
                o[a][0] += pa*v4.x; o[a][1] += pa*v4.y;
                o[a][2] += pa*v4.z; o[a][3] += pa*v4.w;
            }
        }
    }

    #pragma unroll
    for (int a = 0; a < 4; a++) {
        float lt = lrow[a];
        lt += __shfl_xor_sync(0xffffffffu, lt, 8);
        lt += __shfl_xor_sync(0xffffffffu, lt, 4);
        lt += __shfl_xor_sync(0xffffffffu, lt, 2);
        lt += __shfl_xor_sync(0xffffffffu, lt, 1);
        float inv = 1.f / lt;
        float4 v = make_float4(o[a][0]*inv, o[a][1]*inv, o[a][2]*inv, o[a][3]*inv);
        size_t row = (size_t)(i0 + (ty<<2) + a)*BATCH + b;
        *(float4*)&g_AV[row*DM + n*DH + (tx<<2)] = v;
    }
}

// LayerNorm over g_O rows -> d_out
__global__ __launch_bounds__(256)
void k_ln(const float* __restrict__ gamma, const float* __restrict__ beta,
          float* __restrict__ out)
{
    __shared__ float red[16];
    const int t = threadIdx.x;
    const size_t row = blockIdx.x;
    float4 x = *(const float4*)&g_O[row*DM + t*4];
    float s = x.x + x.y + x.z + x.w;
    float ss = x.x*x.x + x.y*x.y + x.z*x.z + x.w*x.w;
    #pragma unroll
    for (int m = 16; m > 0; m >>= 1) {
        s  += __shfl_xor_sync(0xffffffffu, s, m);
        ss += __shfl_xor_sync(0xffffffffu, ss, m);
    }
    if ((t&31) == 0) { red[t>>5] = s; red[8 + (t>>5)] = ss; }
    __syncthreads();
    if (t < 8) {
        float a = red[t], bsum = red[8+t];
        #pragma unroll
        for (int m = 4; m > 0; m >>= 1) {
            a    += __shfl_xor_sync(0xffu, a, m);
            bsum += __shfl_xor_sync(0xffu, bsum, m);
        }
        if (t == 0) { red[0] = a; red[8] = bsum; }
    }
    __syncthreads();
    float mu = red[0] * (1.f/DM);
    float var = red[8] * (1.f/DM) - mu*mu;
    float rs = rsqrtf(var + 1e-5f);
    float4 g = *(const float4*)&gamma[t*4];
    float4 be = *(const float4*)&beta[t*4];
    float4 y;
    y.x = (x.x-mu)*rs*g.x + be.x;
    y.y = (x.y-mu)*rs*g.y + be.y;
    y.z = (x.z-mu)*rs*g.z + be.z;
    y.w = (x.w-mu)*rs*g.w + be.w;
    *(float4*)&out[row*DM + t*4] = y;
}

extern "C" void kernel_launch(void* const* d_in, const int* in_sizes, int n_in,
                              void* d_out, int out_size)
{
    const float* content = (const float*)d_in[0];
    const float* rel_pos = (const float*)d_in[1];
    const float* mems    = (const float*)d_in[2];
    const float* rwb     = (const float*)d_in[3];
    const float* rrb     = (const float*)d_in[4];
    const float* Wqkv    = (const float*)d_in[5];
    const float* Wr      = (const float*)d_in[6];
    const float* Wo      = (const float*)d_in[7];
    const float* gamma   = (const float*)d_in[8];
    const float* beta    = (const float*)d_in[9];
    float* out = (float*)d_out;

    cudaFuncSetAttribute(k_attn, cudaFuncAttributeMaxDynamicSharedMemorySize, SMEM_ATTN);

    k_qkv  <<<dim3(24, 64), 256>>>(content, mems, Wqkv);
    k_rproj<<<dim3(8, 16),  256>>>(rel_pos, Wr);
    k_attn <<<dim3(QLEN/64, NH, BATCH), 256, SMEM_ATTN>>>(rwb, rrb);
    k_out  <<<dim3(8, 32),  256>>>(content, Wo);
    k_ln   <<<QLEN*BATCH, 256>>>(gamma, beta, out);
}

// round 7
// speedup vs baseline: 1.1109x; 1.1109x over previous
#include <cuda_runtime.h>
#include <cstdint>

#define QLEN  1024
#define MLEN  1024
#define KLENN 2048
#define BATCH 4
#define NH    16
#define DH    64
#define DM    1024

// Scratch: no allocation allowed -> device globals.
__device__ float g_Q[BATCH*NH*QLEN*DH];
__device__ float g_K[BATCH*NH*KLENN*DH];
__device__ float g_V[BATCH*NH*KLENN*DH];
__device__ float g_R[NH*KLENN*DH];
__device__ float g_AV[QLEN*BATCH*DM];
__device__ float g_O[QLEN*BATCH*DM];
// Pre-split tf32 hi/lo planes.
__device__ float g_Ah[8192*DM],  g_Al[8192*DM];    // cat([mems;content])
__device__ float g_W3h[DM*3072], g_W3l[DM*3072];   // W_qkv
__device__ float g_Rph[KLENN*DM],g_Rpl[KLENN*DM];  // rel_pos
__device__ float g_Wrh[DM*DM],   g_Wrl[DM*DM];     // W_r
__device__ float g_Woh[DM*DM],   g_Wol[DM*DM];     // W_o
__device__ float g_AVh[4096*DM], g_AVl[4096*DM];   // attn_vec

__device__ __forceinline__ float ex2(float x) {
    float y; asm("ex2.approx.ftz.f32 %0, %1;" : "=f"(y) : "f"(x)); return y;
}

__device__ __forceinline__ void tf32_split(float x, float& hi, float& lo) {
    uint32_t b;
    asm("cvt.rna.tf32.f32 %0, %1;" : "=r"(b) : "f"(x));
    hi = __uint_as_float(b);
    float r = x - hi;
    uint32_t b2;
    asm("cvt.rna.tf32.f32 %0, %1;" : "=r"(b2) : "f"(r));
    lo = __uint_as_float(b2);
}

__device__ __forceinline__ void mma8(float c[4],
    uint32_t a0, uint32_t a1, uint32_t a2, uint32_t a3,
    uint32_t b0, uint32_t b1)
{
    asm volatile(
        "mma.sync.aligned.m16n8k8.row.col.f32.tf32.tf32.f32 "
        "{%0,%1,%2,%3}, {%4,%5,%6,%7}, {%8,%9}, {%0,%1,%2,%3};"
        : "+f"(c[0]), "+f"(c[1]), "+f"(c[2]), "+f"(c[3])
        : "r"(a0), "r"(a1), "r"(a2), "r"(a3), "r"(b0), "r"(b1));
}

// Elementwise hi/lo split (float4 granularity).
__global__ __launch_bounds__(256)
void k_split(const float* __restrict__ src, float* __restrict__ hi,
             float* __restrict__ lo, int n4)
{
    int i = blockIdx.x*256 + threadIdx.x;
    if (i < n4) {
        float4 v = ((const float4*)src)[i];
        float4 h, l;
        tf32_split(v.x, h.x, l.x);
        tf32_split(v.y, h.y, l.y);
        tf32_split(v.z, h.z, l.z);
        tf32_split(v.w, h.w, l.w);
        ((float4*)hi)[i] = h;
        ((float4*)lo)[i] = l;
    }
}

// ---------------------------------------------------------------------------
// 128x128 3xTF32 GEMM, pre-split planes, register-prefetch double buffering.
// Warp grid 2x4 (warp tile 64x32). AP=136 -> conflict-free fragment LDS.
// ---------------------------------------------------------------------------
#define AP 136

__device__ __forceinline__ void gemm_pre(
    const float* __restrict__ Ah, const float* __restrict__ Al, size_t arow,
    const float* __restrict__ Bh, const float* __restrict__ Bl, int ldb, int n0,
    float (&C)[4][4][4],
    float (*AsB)[AP], float (*AsS)[AP], float (*BsB)[AP], float (*BsS)[AP],
    int t)
{
    const int ar=t>>1, ac=(t&1)<<3, br=t>>5, bc=(t&31)<<2;
    const int lane=t&31, w=t>>5, wm=w>>2, wn=w&3;
    const int tig=lane&3, grp=lane>>2;

    const float* ah = Ah + arow*DM + ac;
    const float* al = Al + arow*DM + ac;
    const float* bh = Bh + (size_t)br*ldb + n0 + bc;
    const float* bl = Bl + (size_t)br*ldb + n0 + bc;
    const size_t b8 = (size_t)8*ldb;

    float4 pAh0 = *(const float4*)(ah);
    float4 pAh1 = *(const float4*)(ah+4);
    float4 pAl0 = *(const float4*)(al);
    float4 pAl1 = *(const float4*)(al+4);
    float4 pBh0 = *(const float4*)(bh);
    float4 pBh1 = *(const float4*)(bh + b8);
    float4 pBl0 = *(const float4*)(bl);
    float4 pBl1 = *(const float4*)(bl + b8);

    for (int kt = 0; kt < DM; kt += 16) {
        __syncthreads();
        AsB[ac+0][ar]=pAh0.x; AsB[ac+1][ar]=pAh0.y; AsB[ac+2][ar]=pAh0.z; AsB[ac+3][ar]=pAh0.w;
        AsB[ac+4][ar]=pAh1.x; AsB[ac+5][ar]=pAh1.y; AsB[ac+6][ar]=pAh1.z; AsB[ac+7][ar]=pAh1.w;
        AsS[ac+0][ar]=pAl0.x; AsS[ac+1][ar]=pAl0.y; AsS[ac+2][ar]=pAl0.z; AsS[ac+3][ar]=pAl0.w;
        AsS[ac+4][ar]=pAl1.x; AsS[ac+5][ar]=pAl1.y; AsS[ac+6][ar]=pAl1.z; AsS[ac+7][ar]=pAl1.w;
        *(float4*)&BsB[br  ][bc] = pBh0;
        *(float4*)&BsB[br+8][bc] = pBh1;
        *(float4*)&BsS[br  ][bc] = pBl0;
        *(float4*)&BsS[br+8][bc] = pBl1;
        __syncthreads();

        if (kt + 16 < DM) {
            int k2 = kt + 16;
            size_t bo = (size_t)k2*ldb;
            pAh0 = *(const float4*)(ah + k2);
            pAh1 = *(const float4*)(ah + k2 + 4);
            pAl0 = *(const float4*)(al + k2);
            pAl1 = *(const float4*)(al + k2 + 4);
            pBh0 = *(const float4*)(bh + bo);
            pBh1 = *(const float4*)(bh + bo + b8);
            pBl0 = *(const float4*)(bl + bo);
            pBl1 = *(const float4*)(bl + bo + b8);
        }

        #pragma unroll
        for (int k8 = 0; k8 < 16; k8 += 8) {
            uint32_t aB[4][4], aS[4][4], bB[4][2], bS[4][2];
            #pragma unroll
            for (int mt = 0; mt < 4; mt++) {
                int m0 = wm*64 + mt*16 + grp;
                aB[mt][0] = __float_as_uint(AsB[k8+tig  ][m0  ]);
                aB[mt][1] = __float_as_uint(AsB[k8+tig  ][m0+8]);
                aB[mt][2] = __float_as_uint(AsB[k8+tig+4][m0  ]);
                aB[mt][3] = __float_as_uint(AsB[k8+tig+4][m0+8]);
                aS[mt][0] = __float_as_uint(AsS[k8+tig  ][m0  ]);
                aS[mt][1] = __float_as_uint(AsS[k8+tig  ][m0+8]);
                aS[mt][2] = __float_as_uint(AsS[k8+tig+4][m0  ]);
                aS[mt][3] = __float_as_uint(AsS[k8+tig+4][m0+8]);
            }
            #pragma unroll
            for (int nt = 0; nt < 4; nt++) {
                int nc = wn*32 + nt*8 + grp;
                bB[nt][0] = __float_as_uint(BsB[k8+tig  ][nc]);
                bB[nt][1] = __float_as_uint(BsB[k8+tig+4][nc]);
                bS[nt][0] = __float_as_uint(BsS[k8+tig  ][nc]);
                bS[nt][1] = __float_as_uint(BsS[k8+tig+4][nc]);
            }
            #pragma unroll
            for (int mt = 0; mt < 4; mt++) {
                #pragma unroll
                for (int nt = 0; nt < 4; nt++) {
                    mma8(C[mt][nt], aB[mt][0],aB[mt][1],aB[mt][2],aB[mt][3], bB[nt][0],bB[nt][1]);
                    mma8(C[mt][nt], aB[mt][0],aB[mt][1],aB[mt][2],aB[mt][3], bS[nt][0],bS[nt][1]);
                    mma8(C[mt][nt], aS[mt][0],aS[mt][1],aS[mt][2],aS[mt][3], bB[nt][0],bB[nt][1]);
                }
            }
        }
    }
}

// GEMM 1: cat @ W_qkv -> scatter g_Q/g_K/g_V.
__global__ __launch_bounds__(256)
void k_qkv()
{
    __shared__ float AsB[16][AP], AsS[16][AP], BsB[16][AP], BsS[16][AP];
    const int t = threadIdx.x, n0 = blockIdx.x<<7, m0 = blockIdx.y<<7;
    const int lane = t&31, w = t>>5, wm = w>>2, wn = w&3;
    const int tig = lane&3, grp = lane>>2;
    float C[4][4][4];
    #pragma unroll
    for (int i = 0; i < 4; i++) {
        #pragma unroll
        for (int j = 0; j < 4; j++) {
            #pragma unroll
            for (int k = 0; k < 4; k++) C[i][j][k] = 0.f;
        }
    }
    gemm_pre(g_Ah, g_Al, (size_t)(m0 + (t>>1)), g_W3h, g_W3l, 3072, n0,
             C, AsB, AsS, BsB, BsS, t);

    #pragma unroll
    for (int mt = 0; mt < 4; mt++) {
        #pragma unroll
        for (int h = 0; h < 2; h++) {
            int m = m0 + wm*64 + mt*16 + grp + 8*h;
            int row = m >> 2, bb = m & 3;
            #pragma unroll
            for (int nt = 0; nt < 4; nt++) {
                int col = n0 + wn*32 + nt*8 + 2*tig;
                int sec = col >> 10, nn = (col>>6)&15, dd = col & 63;
                float2 v = make_float2(C[mt][nt][2*h], C[mt][nt][2*h+1]);
                if (sec == 0) {
                    if (row >= MLEN)
                        *(float2*)&g_Q[(((size_t)bb*NH+nn)*QLEN + (row-MLEN))*DH + dd] = v;
                } else if (sec == 1) {
                    *(float2*)&g_K[(((size_t)bb*NH+nn)*KLENN + row)*DH + dd] = v;
                } else {
                    *(float2*)&g_V[(((size_t)bb*NH+nn)*KLENN + row)*DH + dd] = v;
                }
            }
        }
    }
}

// GEMM 2: rel_pos @ W_r -> g_R[n][m][d]
__global__ __launch_bounds__(256)
void k_rproj()
{
    __shared__ float AsB[16][AP], AsS[16][AP], BsB[16][AP], BsS[16][AP];
    const int t = threadIdx.x, n0 = blockIdx.x<<7, m0 = blockIdx.y<<7;
    const int lane = t&31, w = t>>5, wm = w>>2, wn = w&3;
    const int tig = lane&3, grp = lane>>2;
    float C[4][4][4];
    #pragma unroll
    for (int i = 0; i < 4; i++) {
        #pragma unroll
        for (int j = 0; j < 4; j++) {
            #pragma unroll
            for (int k = 0; k < 4; k++) C[i][j][k] = 0.f;
        }
    }
    gemm_pre(g_Rph, g_Rpl, (size_t)(m0 + (t>>1)), g_Wrh, g_Wrl, DM, n0,
             C, AsB, AsS, BsB, BsS, t);

    #pragma unroll
    for (int mt = 0; mt < 4; mt++) {
        #pragma unroll
        for (int h = 0; h < 2; h++) {
            int m = m0 + wm*64 + mt*16 + grp + 8*h;
            #pragma unroll
            for (int nt = 0; nt < 4; nt++) {
                int col = n0 + wn*32 + nt*8 + 2*tig;
                int nn = col >> 6, dd = col & 63;
                float2 v = make_float2(C[mt][nt][2*h], C[mt][nt][2*h+1]);
                *(float2*)&g_R[((size_t)nn*KLENN + m)*DH + dd] = v;
            }
        }
    }
}

// GEMM 3: g_AV @ W_o + content -> g_O
__global__ __launch_bounds__(256)
void k_out(const float* __restrict__ content)
{
    __shared__ float AsB[16][AP], AsS[16][AP], BsB[16][AP], BsS[16][AP];
    const int t = threadIdx.x, n0 = blockIdx.x<<7, m0 = blockIdx.y<<7;
    const int lane = t&31, w = t>>5, wm = w>>2, wn = w&3;
    const int tig = lane&3, grp = lane>>2;
    float C[4][4][4];
    #pragma unroll
    for (int i = 0; i < 4; i++) {
        #pragma unroll
        for (int j = 0; j < 4; j++) {
            #pragma unroll
            for (int k = 0; k < 4; k++) C[i][j][k] = 0.f;
        }
    }
    gemm_pre(g_AVh, g_AVl, (size_t)(m0 + (t>>1)), g_Woh, g_Wol, DM, n0,
             C, AsB, AsS, BsB, BsS, t);

    #pragma unroll
    for (int mt = 0; mt < 4; mt++) {
        #pragma unroll
        for (int h = 0; h < 2; h++) {
            size_t m = m0 + wm*64 + mt*16 + grp + 8*h;
            #pragma unroll
            for (int nt = 0; nt < 4; nt++) {
                int col = n0 + wn*32 + nt*8 + 2*tig;
                float2 c4 = *(const float2*)(content + m*DM + col);
                float2 v = make_float2(C[mt][nt][2*h] + c4.x, C[mt][nt][2*h+1] + c4.y);
                *(float2*)&g_O[m*DM + col] = v;
            }
        }
    }
}

// ---------------------------------------------------------------------------
// Fused flash attention with Transformer-XL rel-shift (fp32, unchanged).
// ---------------------------------------------------------------------------
#define SMF_QA 0
#define SMF_QB 4096
#define SMF_KT 8192
#define SMF_VT 12288
#define SMF_RT 16384
#define SMF_PS 24576
#define SMEM_ATTN ((24576 + 64*68) * 4)

__global__ __launch_bounds__(256)
void k_attn(const float* __restrict__ rwb, const float* __restrict__ rrb)
{
    extern __shared__ float smf[];
    float* qaT = smf + SMF_QA;
    float* qbT = smf + SMF_QB;
    float* ktT = smf + SMF_KT;
    float* vt  = smf + SMF_VT;
    float* rtT = smf + SMF_RT;
    float* ps  = smf + SMF_PS;

    const int t = threadIdx.x, lane = t&31, w = t>>5, tx = t&15, ty = t>>4;
    const int i0 = blockIdx.x<<6, n = blockIdx.y, b = blockIdx.z;

    const float* Qb = g_Q + (size_t)(b*NH+n)*QLEN*DH;
    const float* Kb = g_K + (size_t)(b*NH+n)*KLENN*DH;
    const float* Vb = g_V + (size_t)(b*NH+n)*KLENN*DH;
    const float* Rb = g_R + (size_t)n*KLENN*DH;

    {
        int qrow = lane + ((w>>2)<<5);
        int d0 = (w&3)<<4;
        const float* qp = Qb + (size_t)(i0+qrow)*DH + d0;
        #pragma unroll
        for (int u = 0; u < 4; u++) {
            float4 v = *(const float4*)(qp + 4*u);
            int d = d0 + 4*u;
            qaT[(d+0)*64+qrow]=v.x+rwb[n*DH+d+0]; qbT[(d+0)*64+qrow]=v.x+rrb[n*DH+d+0];
            qaT[(d+1)*64+qrow]=v.y+rwb[n*DH+d+1]; qbT[(d+1)*64+qrow]=v.y+rrb[n*DH+d+1];
            qaT[(d+2)*64+qrow]=v.z+rwb[n*DH+d+2]; qbT[(d+2)*64+qrow]=v.z+rrb[n*DH+d+2];
            qaT[(d+3)*64+qrow]=v.w+rwb[n*DH+d+3]; qbT[(d+3)*64+qrow]=v.w+rrb[n*DH+d+3];
        }
    }

    float mrow[4], lrow[4], o[4][4];
    #pragma unroll
    for (int a = 0; a < 4; a++) {
        mrow[a] = -1e30f; lrow[a] = 0.f;
        #pragma unroll
        for (int c = 0; c < 4; c++) o[a][c] = 0.f;
    }

    const float fscale = 0.18033688011112042f;
    const int ntiles = (i0>>6) + 17;
    const int rb4 = ((tx - ty)<<2) + 60;

    for (int tile = 0; tile < ntiles; tile++) {
        const int j0 = tile<<6;
        __syncthreads();
        {
            int jc = lane + ((w>>2)<<5); int d0 = (w&3)<<4;
            const float* kp = Kb + (size_t)(j0+jc)*DH + d0;
            #pragma unroll
            for (int u = 0; u < 4; u++) {
                float4 v = *(const float4*)(kp + 4*u); int d = d0 + 4*u;
                ktT[(d+0)*64+jc]=v.x; ktT[(d+1)*64+jc]=v.y;
                ktT[(d+2)*64+jc]=v.z; ktT[(d+3)*64+jc]=v.w;
            }
        }
        {
            int jc = t>>2; int d0 = (t&3)<<4;
            const float* vp = Vb + (size_t)(j0+jc)*DH + d0;
            #pragma unroll
            for (int u = 0; u < 4; u++)
                *(float4*)&vt[jc*64 + d0 + 4*u] = *(const float4*)(vp + 4*u);
        }
        {
            int rr = lane + ((w>>1)<<5); int d0 = (w&1)<<5;
            int mg = j0 + 960 - i0 + rr;
            #pragma unroll
            for (int u = 0; u < 8; u++) {
                int d = d0 + 4*u;
                float4 v = make_float4(0.f,0.f,0.f,0.f);
                if (mg < KLENN) v = *(const float4*)(Rb + (size_t)mg*DH + d);
                rtT[(d+0)*128+rr]=v.x; rtT[(d+1)*128+rr]=v.y;
                rtT[(d+2)*128+rr]=v.z; rtT[(d+3)*128+rr]=v.w;
            }
        }
        __syncthreads();

        float acc[4][4];
        #pragma unroll
        for (int a = 0; a < 4; a++) {
            #pragma unroll
            for (int c = 0; c < 4; c++) acc[a][c] = 0.f;
        }
        #pragma unroll 8
        for (int d = 0; d < 64; d++) {
            float4 qa4 = *(const float4*)&qaT[d*64 + (ty<<2)];
            float4 qb4 = *(const float4*)&qbT[d*64 + (ty<<2)];
            float4 kk4 = *(const float4*)&ktT[d*64 + (tx<<2)];
            float4 r04 = *(const float4*)&rtT[d*128 + rb4];
            float4 r14 = *(const float4*)&rtT[d*128 + rb4 + 4];
            float qaa[4]={qa4.x,qa4.y,qa4.z,qa4.w};
            float qbb[4]={qb4.x,qb4.y,qb4.z,qb4.w};
            float kkk[4]={kk4.x,kk4.y,kk4.z,kk4.w};
            float rr7[7]={r04.x,r04.y,r04.z,r04.w,r14.x,r14.y,r14.z};
            #pragma unroll
            for (int a = 0; a < 4; a++) {
                #pragma unroll
                for (int c = 0; c < 4; c++)
                    acc[a][c] += qaa[a]*kkk[c] + qbb[a]*rr7[c-a+3];
            }
        }

        #pragma unroll
        for (int a = 0; a < 4; a++) {
            const int iq = i0 + (ty<<2) + a;
            float s[4];
            #pragma unroll
            for (int c = 0; c < 4; c++) {
                int jk = j0 + (tx<<2) + c;
                s[c] = (jk > iq + MLEN) ? -1e30f : acc[a][c]*fscale;
            }
            float tm = fmaxf(fmaxf(s[0],s[1]), fmaxf(s[2],s[3]));
            tm = fmaxf(tm, __shfl_xor_sync(0xffffffffu, tm, 8));
            tm = fmaxf(tm, __shfl_xor_sync(0xffffffffu, tm, 4));
            tm = fmaxf(tm, __shfl_xor_sync(0xffffffffu, tm, 2));
            tm = fmaxf(tm, __shfl_xor_sync(0xffffffffu, tm, 1));
            float mn = fmaxf(mrow[a], tm);
            float cf = ex2(mrow[a] - mn);
            mrow[a] = mn;
            float p0=ex2(s[0]-mn), p1=ex2(s[1]-mn), p2=ex2(s[2]-mn), p3=ex2(s[3]-mn);
            lrow[a] = lrow[a]*cf + (p0+p1+p2+p3);
            #pragma unroll
            for (int c = 0; c < 4; c++) o[a][c] *= cf;
            *(float4*)&ps[((ty<<2)+a)*68 + (tx<<2)] = make_float4(p0,p1,p2,p3);
        }
        __syncthreads();

        #pragma unroll 4
        for (int j = 0; j < 64; j++) {
            float4 v4 = *(const float4*)&vt[j*64 + (tx<<2)];
            #pragma unroll
            for (int a = 0; a < 4; a++) {
                float pa = ps[((ty<<2)+a)*68 + j];
                o[a][0] += pa*v4.x; o[a][1] += pa*v4.y;
                o[a][2] += pa*v4.z; o[a][3] += pa*v4.w;
            }
        }
    }

    #pragma unroll
    for (int a = 0; a < 4; a++) {
        float lt = lrow[a];
        lt += __shfl_xor_sync(0xffffffffu, lt, 8);
        lt += __shfl_xor_sync(0xffffffffu, lt, 4);
        lt += __shfl_xor_sync(0xffffffffu, lt, 2);
        lt += __shfl_xor_sync(0xffffffffu, lt, 1);
        float inv = 1.f / lt;
        float4 v = make_float4(o[a][0]*inv, o[a][1]*inv, o[a][2]*inv, o[a][3]*inv);
        size_t row = (size_t)(i0 + (ty<<2) + a)*BATCH + b;
        *(float4*)&g_AV[row*DM + n*DH + (tx<<2)] = v;
    }
}

// LayerNorm over g_O rows -> d_out
__global__ __launch_bounds__(256)
void k_ln(const float* __restrict__ gamma, const float* __restrict__ beta,
          float* __restrict__ out)
{
    __shared__ float red[16];
    const int t = threadIdx.x;
    const size_t row = blockIdx.x;
    float4 x = *(const float4*)&g_O[row*DM + t*4];
    float s = x.x + x.y + x.z + x.w;
    float ss = x.x*x.x + x.y*x.y + x.z*x.z + x.w*x.w;
    #pragma unroll
    for (int m = 16; m > 0; m >>= 1) {
        s  += __shfl_xor_sync(0xffffffffu, s, m);
        ss += __shfl_xor_sync(0xffffffffu, ss, m);
    }
    if ((t&31) == 0) { red[t>>5] = s; red[8 + (t>>5)] = ss; }
    __syncthreads();
    if (t < 8) {
        float a = red[t], bsum = red[8+t];
        #pragma unroll
        for (int m = 4; m > 0; m >>= 1) {
            a    += __shfl_xor_sync(0xffu, a, m);
            bsum += __shfl_xor_sync(0xffu, bsum, m);
        }
        if (t == 0) { red[0] = a; red[8] = bsum; }
    }
    __syncthreads();
    float mu = red[0] * (1.f/DM);
    float var = red[8] * (1.f/DM) - mu*mu;
    float rs = rsqrtf(var + 1e-5f);
    float4 g = *(const float4*)&gamma[t*4];
    float4 be = *(const float4*)&beta[t*4];
    float4 y;
    y.x = (x.x-mu)*rs*g.x + be.x;
    y.y = (x.y-mu)*rs*g.y + be.y;
    y.z = (x.z-mu)*rs*g.z + be.z;
    y.w = (x.w-mu)*rs*g.w + be.w;
    *(float4*)&out[row*DM + t*4] = y;
}

extern "C" void kernel_launch(void* const* d_in, const int* in_sizes, int n_in,
                              void* d_out, int out_size)
{
    const float* content = (const float*)d_in[0];
    const float* rel_pos = (const float*)d_in[1];
    const float* mems    = (const float*)d_in[2];
    const float* rwb     = (const float*)d_in[3];
    const float* rrb     = (const float*)d_in[4];
    const float* Wqkv    = (const float*)d_in[5];
    const float* Wr      = (const float*)d_in[6];
    const float* Wo      = (const float*)d_in[7];
    const float* gamma   = (const float*)d_in[8];
    const float* beta    = (const float*)d_in[9];
    float* out = (float*)d_out;

    cudaFuncSetAttribute(k_attn, cudaFuncAttributeMaxDynamicSharedMemorySize, SMEM_ATTN);

    float *Ah, *Al, *W3h, *W3l, *Rph, *Rpl, *Wrh, *Wrl, *Woh, *Wol, *AVh, *AVl, *AV;
    cudaGetSymbolAddress((void**)&Ah,  g_Ah);
    cudaGetSymbolAddress((void**)&Al,  g_Al);
    cudaGetSymbolAddress((void**)&W3h, g_W3h);
    cudaGetSymbolAddress((void**)&W3l, g_W3l);
    cudaGetSymbolAddress((void**)&Rph, g_Rph);
    cudaGetSymbolAddress((void**)&Rpl, g_Rpl);
    cudaGetSymbolAddress((void**)&Wrh, g_Wrh);
    cudaGetSymbolAddress((void**)&Wrl, g_Wrl);
    cudaGetSymbolAddress((void**)&Woh, g_Woh);
    cudaGetSymbolAddress((void**)&Wol, g_Wol);
    cudaGetSymbolAddress((void**)&AVh, g_AVh);
    cudaGetSymbolAddress((void**)&AVl, g_AVl);
    cudaGetSymbolAddress((void**)&AV,  g_AV);

    const int MB = 4096*DM/4;  // float4 count for 4096x1024
    // Split inputs into tf32 hi/lo planes.
    k_split<<<(MB+255)/256, 256>>>(mems,    Ah,              Al,              MB);
    k_split<<<(MB+255)/256, 256>>>(content, Ah + 4096*DM,    Al + 4096*DM,    MB);
    k_split<<<(DM*3072/4+255)/256, 256>>>(Wqkv,    W3h, W3l, DM*3072/4);
    k_split<<<(KLENN*DM/4+255)/256, 256>>>(rel_pos, Rph, Rpl, KLENN*DM/4);
    k_split<<<(DM*DM/4+255)/256, 256>>>(Wr, Wrh, Wrl, DM*DM/4);
    k_split<<<(DM*DM/4+255)/256, 256>>>(Wo, Woh, Wol, DM*DM/4);

    k_qkv  <<<dim3(24, 64), 256>>>();
    k_rproj<<<dim3(8, 16),  256>>>();
    k_attn <<<dim3(QLEN/64, NH, BATCH), 256, SMEM_ATTN>>>(rwb, rrb);
    k_split<<<(MB+255)/256, 256>>>(AV, AVh, AVl, MB);
    k_out  <<<dim3(8, 32),  256>>>(content);
    k_ln   <<<QLEN*BATCH, 256>>>(gamma, beta, out);
}

// round 8
// speedup vs baseline: 1.5565x; 1.4011x over previous
#include <cuda_runtime.h>
#include <cuda_bf16.h>
#include <cstdint>

#define QLEN  1024
#define MLEN  1024
#define KLENN 2048
#define BATCH 4
#define NH    16
#define DH    64
#define DM    1024

// fp32 scratch
__device__ float g_Q[BATCH*NH*QLEN*DH];
__device__ float g_K[BATCH*NH*KLENN*DH];
__device__ float g_V[BATCH*NH*KLENN*DH];
__device__ float g_R[NH*KLENN*DH];
__device__ float g_AV[QLEN*BATCH*DM];
__device__ float g_O[QLEN*BATCH*DM];
// bf16 hi/lo planes
__device__ __nv_bfloat16 g_Ah[8192*DM],  g_Al[8192*DM];
__device__ __nv_bfloat16 g_W3h[DM*3072], g_W3l[DM*3072];
__device__ __nv_bfloat16 g_Rph[KLENN*DM],g_Rpl[KLENN*DM];
__device__ __nv_bfloat16 g_Wrh[DM*DM],   g_Wrl[DM*DM];
__device__ __nv_bfloat16 g_Woh[DM*DM],   g_Wol[DM*DM];
__device__ __nv_bfloat16 g_AVh[4096*DM], g_AVl[4096*DM];

__device__ __forceinline__ float ex2(float x) {
    float y; asm("ex2.approx.ftz.f32 %0, %1;" : "=f"(y) : "f"(x)); return y;
}

// ---------------------------------------------------------------------------
// bf16 split kernel: hi = bf16(x), lo = bf16(x - hi)
// ---------------------------------------------------------------------------
__global__ __launch_bounds__(256)
void k_splitb(const float* __restrict__ src, __nv_bfloat16* __restrict__ hi,
              __nv_bfloat16* __restrict__ lo, int n4)
{
    int i = blockIdx.x*256 + threadIdx.x;
    if (i < n4) {
        float4 v = ((const float4*)src)[i];
        float f[4] = {v.x, v.y, v.z, v.w};
        uint32_t hp[2], lp[2];
        #pragma unroll
        for (int p = 0; p < 2; p++) {
            __nv_bfloat16 h0 = __float2bfloat16(f[2*p]);
            __nv_bfloat16 h1 = __float2bfloat16(f[2*p+1]);
            __nv_bfloat16 l0 = __float2bfloat16(f[2*p]   - __bfloat162float(h0));
            __nv_bfloat16 l1 = __float2bfloat16(f[2*p+1] - __bfloat162float(h1));
            hp[p] = (uint32_t)__bfloat16_as_ushort(h0) | ((uint32_t)__bfloat16_as_ushort(h1)<<16);
            lp[p] = (uint32_t)__bfloat16_as_ushort(l0) | ((uint32_t)__bfloat16_as_ushort(l1)<<16);
        }
        ((uint2*)hi)[i] = make_uint2(hp[0], hp[1]);
        ((uint2*)lo)[i] = make_uint2(lp[0], lp[1]);
    }
}

// ---------------------------------------------------------------------------
// bf16-split GEMM: 128x128 CTA tile, k-step 32, ldmatrix + cp.async pipeline.
// ---------------------------------------------------------------------------
#define KS 32
#define A_PAD 40
#define B_PAD 136
#define A_PLANE (128*A_PAD)           // bf16 units
#define A_BUF   (2*A_PLANE)
#define B_PLANE (KS*B_PAD)
#define B_BUF   (2*B_PLANE)
#define BUF_ELEMS (A_BUF + B_BUF)
#define SMEM_GEMM (2*BUF_ELEMS*2)     // 75776 bytes

__device__ __forceinline__ void ldsm4(uint32_t (&r)[4], uint32_t addr) {
    asm volatile("ldmatrix.sync.aligned.m8n8.x4.shared.b16 {%0,%1,%2,%3}, [%4];"
        : "=r"(r[0]), "=r"(r[1]), "=r"(r[2]), "=r"(r[3]) : "r"(addr));
}
__device__ __forceinline__ void ldsm4t(uint32_t (&r)[4], uint32_t addr) {
    asm volatile("ldmatrix.sync.aligned.m8n8.x4.trans.shared.b16 {%0,%1,%2,%3}, [%4];"
        : "=r"(r[0]), "=r"(r[1]), "=r"(r[2]), "=r"(r[3]) : "r"(addr));
}
__device__ __forceinline__ void mma16(float (&c)[4], const uint32_t (&a)[4],
                                      uint32_t b0, uint32_t b1) {
    asm volatile(
        "mma.sync.aligned.m16n8k16.row.col.f32.bf16.bf16.f32 "
        "{%0,%1,%2,%3},{%4,%5,%6,%7},{%8,%9},{%0,%1,%2,%3};"
        : "+f"(c[0]), "+f"(c[1]), "+f"(c[2]), "+f"(c[3])
        : "r"(a[0]), "r"(a[1]), "r"(a[2]), "r"(a[3]), "r"(b0), "r"(b1));
}

__device__ __forceinline__ void cta_load(
    uint32_t sb, int buf,
    const __nv_bfloat16* __restrict__ Ah, const __nv_bfloat16* __restrict__ Al, size_t m0,
    const __nv_bfloat16* __restrict__ Bh, const __nv_bfloat16* __restrict__ Bl,
    int ldb, int n0, int kt, int t)
{
    uint32_t bo = sb + (uint32_t)buf * (BUF_ELEMS*2);
    #pragma unroll
    for (int i = 0; i < 4; i++) {           // A: 1024 x 16B chunks
        int c = t + 256*i;
        int p = c >> 9, rc = c & 511;
        int row = rc >> 2, seg = rc & 3;
        const __nv_bfloat16* src = (p ? Al : Ah) + (m0 + row)*DM + kt + seg*8;
        uint32_t dst = bo + (uint32_t)(p*A_PLANE + row*A_PAD + seg*8)*2;
        asm volatile("cp.async.cg.shared.global [%0], [%1], 16;" :: "r"(dst), "l"(src));
    }
    #pragma unroll
    for (int i = 0; i < 4; i++) {           // B: 1024 x 16B chunks
        int c = t + 256*i;
        int p = c >> 9, rc = c & 511;
        int row = rc >> 4, seg = rc & 15;
        const __nv_bfloat16* src = (p ? Bl : Bh) + (size_t)(kt + row)*ldb + n0 + seg*8;
        uint32_t dst = bo + (uint32_t)(A_BUF*2 + (p*B_PLANE + row*B_PAD + seg*8)*2);
        asm volatile("cp.async.cg.shared.global [%0], [%1], 16;" :: "r"(dst), "l"(src));
    }
}

__device__ __forceinline__ void gemm_bf16(
    const __nv_bfloat16* __restrict__ Ah, const __nv_bfloat16* __restrict__ Al, size_t m0,
    const __nv_bfloat16* __restrict__ Bh, const __nv_bfloat16* __restrict__ Bl,
    int ldb, int n0, float (&C)[4][4][4], char* smem, int t)
{
    uint32_t sb = (uint32_t)__cvta_generic_to_shared(smem);
    const int lane = t&31, w = t>>5, wm = w>>2, wn = w&3;
    const uint32_t aBase = (uint32_t)(((wm*64 + (lane&15))*A_PAD + ((lane>>4)<<3))*2);
    const uint32_t bBase = (uint32_t)(A_BUF*2 + (((lane&15))*B_PAD + wn*32 + ((lane>>4)<<3))*2);

    cta_load(sb, 0, Ah, Al, m0, Bh, Bl, ldb, n0, 0, t);
    asm volatile("cp.async.commit_group;");

    for (int it = 0; it < DM/KS; ++it) {
        int buf = it & 1;
        if (it + 1 < DM/KS) {
            cta_load(sb, 1-buf, Ah, Al, m0, Bh, Bl, ldb, n0, (it+1)*KS, t);
            asm volatile("cp.async.commit_group;");
            asm volatile("cp.async.wait_group 1;");
        } else {
            asm volatile("cp.async.wait_group 0;");
        }
        __syncthreads();

        uint32_t bo = sb + (uint32_t)buf*(BUF_ELEMS*2);
        #pragma unroll
        for (int c16 = 0; c16 < 2; c16++) {
            uint32_t bb = bo + bBase + (uint32_t)(c16*16*B_PAD*2);
            uint32_t bH0[4], bS0[4], bH1[4], bS1[4];
            ldsm4t(bH0, bb);
            ldsm4t(bS0, bb + B_PLANE*2);
            ldsm4t(bH1, bb + 32);
            ldsm4t(bS1, bb + 32 + B_PLANE*2);
            #pragma unroll
            for (int mt = 0; mt < 4; mt++) {
                uint32_t ab = bo + aBase + (uint32_t)(mt*16*A_PAD*2 + c16*32);
                uint32_t aH[4], aS[4];
                ldsm4(aH, ab);
                ldsm4(aS, ab + A_PLANE*2);
                mma16(C[mt][0], aH, bH0[0], bH0[1]);
                mma16(C[mt][0], aH, bS0[0], bS0[1]);
                mma16(C[mt][0], aS, bH0[0], bH0[1]);
                mma16(C[mt][1], aH, bH0[2], bH0[3]);
                mma16(C[mt][1], aH, bS0[2], bS0[3]);
                mma16(C[mt][1], aS, bH0[2], bH0[3]);
                mma16(C[mt][2], aH, bH1[0], bH1[1]);
                mma16(C[mt][2], aH, bS1[0], bS1[1]);
                mma16(C[mt][2], aS, bH1[0], bH1[1]);
                mma16(C[mt][3], aH, bH1[2], bH1[3]);
                mma16(C[mt][3], aH, bS1[2], bS1[3]);
                mma16(C[mt][3], aS, bH1[2], bH1[3]);
            }
        }
        __syncthreads();
    }
}

// GEMM 1: cat @ W_qkv -> scatter g_Q/g_K/g_V.
__global__ __launch_bounds__(256)
void k_qkv()
{
    extern __shared__ char smg[];
    const int t = threadIdx.x, n0 = blockIdx.x<<7, m0 = blockIdx.y<<7;
    const int lane = t&31, w = t>>5, wm = w>>2, wn = w&3;
    const int tig = lane&3, grp = lane>>2;
    float C[4][4][4];
    #pragma unroll
    for (int i = 0; i < 4; i++) {
        #pragma unroll
        for (int j = 0; j < 4; j++) {
            #pragma unroll
            for (int k = 0; k < 4; k++) C[i][j][k] = 0.f;
        }
    }
    gemm_bf16(g_Ah, g_Al, (size_t)m0, g_W3h, g_W3l, 3072, n0, C, smg, t);

    #pragma unroll
    for (int mt = 0; mt < 4; mt++) {
        #pragma unroll
        for (int h = 0; h < 2; h++) {
            int m = m0 + wm*64 + mt*16 + grp + 8*h;
            int row = m >> 2, bb = m & 3;
            #pragma unroll
            for (int nt = 0; nt < 4; nt++) {
                int col = n0 + wn*32 + nt*8 + 2*tig;
                int sec = col >> 10, nn = (col>>6)&15, dd = col & 63;
                float2 v = make_float2(C[mt][nt][2*h], C[mt][nt][2*h+1]);
                if (sec == 0) {
                    if (row >= MLEN)
                        *(float2*)&g_Q[(((size_t)bb*NH+nn)*QLEN + (row-MLEN))*DH + dd] = v;
                } else if (sec == 1) {
                    *(float2*)&g_K[(((size_t)bb*NH+nn)*KLENN + row)*DH + dd] = v;
                } else {
                    *(float2*)&g_V[(((size_t)bb*NH+nn)*KLENN + row)*DH + dd] = v;
                }
            }
        }
    }
}

// GEMM 2: rel_pos @ W_r -> g_R[n][m][d]
__global__ __launch_bounds__(256)
void k_rproj()
{
    extern __shared__ char smg[];
    const int t = threadIdx.x, n0 = blockIdx.x<<7, m0 = blockIdx.y<<7;
    const int lane = t&31, w = t>>5, wm = w>>2, wn = w&3;
    const int tig = lane&3, grp = lane>>2;
    float C[4][4][4];
    #pragma unroll
    for (int i = 0; i < 4; i++) {
        #pragma unroll
        for (int j = 0; j < 4; j++) {
            #pragma unroll
            for (int k = 0; k < 4; k++) C[i][j][k] = 0.f;
        }
    }
    gemm_bf16(g_Rph, g_Rpl, (size_t)m0, g_Wrh, g_Wrl, DM, n0, C, smg, t);

    #pragma unroll
    for (int mt = 0; mt < 4; mt++) {
        #pragma unroll
        for (int h = 0; h < 2; h++) {
            int m = m0 + wm*64 + mt*16 + grp + 8*h;
            #pragma unroll
            for (int nt = 0; nt < 4; nt++) {
                int col = n0 + wn*32 + nt*8 + 2*tig;
                int nn = col >> 6, dd = col & 63;
                float2 v = make_float2(C[mt][nt][2*h], C[mt][nt][2*h+1]);
                *(float2*)&g_R[((size_t)nn*KLENN + m)*DH + dd] = v;
            }
        }
    }
}

// GEMM 3: g_AV @ W_o + content -> g_O
__global__ __launch_bounds__(256)
void k_out(const float* __restrict__ content)
{
    extern __shared__ char smg[];
    const int t = threadIdx.x, n0 = blockIdx.x<<7, m0 = blockIdx.y<<7;
    const int lane = t&31, w = t>>5, wm = w>>2, wn = w&3;
    const int tig = lane&3, grp = lane>>2;
    float C[4][4][4];
    #pragma unroll
    for (int i = 0; i < 4; i++) {
        #pragma unroll
        for (int j = 0; j < 4; j++) {
            #pragma unroll
            for (int k = 0; k < 4; k++) C[i][j][k] = 0.f;
        }
    }
    gemm_bf16(g_AVh, g_AVl, (size_t)m0, g_Woh, g_Wol, DM, n0, C, smg, t);

    #pragma unroll
    for (int mt = 0; mt < 4; mt++) {
        #pragma unroll
        for (int h = 0; h < 2; h++) {
            size_t m = m0 + wm*64 + mt*16 + grp + 8*h;
            #pragma unroll
            for (int nt = 0; nt < 4; nt++) {
                int col = n0 + wn*32 + nt*8 + 2*tig;
                float2 c4 = *(const float2*)(content + m*DM + col);
                float2 v = make_float2(C[mt][nt][2*h] + c4.x, C[mt][nt][2*h+1] + c4.y);
                *(float2*)&g_O[m*DM + col] = v;
            }
        }
    }
}

// ---------------------------------------------------------------------------
// Fused flash attention with Transformer-XL rel-shift (fp32, unchanged).
// ---------------------------------------------------------------------------
#define SMF_QA 0
#define SMF_QB 4096
#define SMF_KT 8192
#define SMF_VT 12288
#define SMF_RT 16384
#define SMF_PS 24576
#define SMEM_ATTN ((24576 + 64*68) * 4)

__global__ __launch_bounds__(256)
void k_attn(const float* __restrict__ rwb, const float* __restrict__ rrb)
{
    extern __shared__ float smf[];
    float* qaT = smf + SMF_QA;
    float* qbT = smf + SMF_QB;
    float* ktT = smf + SMF_KT;
    float* vt  = smf + SMF_VT;
    float* rtT = smf + SMF_RT;
    float* ps  = smf + SMF_PS;

    const int t = threadIdx.x, lane = t&31, w = t>>5, tx = t&15, ty = t>>4;
    const int i0 = blockIdx.x<<6, n = blockIdx.y, b = blockIdx.z;

    const float* Qb = g_Q + (size_t)(b*NH+n)*QLEN*DH;
    const float* Kb = g_K + (size_t)(b*NH+n)*KLENN*DH;
    const float* Vb = g_V + (size_t)(b*NH+n)*KLENN*DH;
    const float* Rb = g_R + (size_t)n*KLENN*DH;

    {
        int qrow = lane + ((w>>2)<<5);
        int d0 = (w&3)<<4;
        const float* qp = Qb + (size_t)(i0+qrow)*DH + d0;
        #pragma unroll
        for (int u = 0; u < 4; u++) {
            float4 v = *(const float4*)(qp + 4*u);
            int d = d0 + 4*u;
            qaT[(d+0)*64+qrow]=v.x+rwb[n*DH+d+0]; qbT[(d+0)*64+qrow]=v.x+rrb[n*DH+d+0];
            qaT[(d+1)*64+qrow]=v.y+rwb[n*DH+d+1]; qbT[(d+1)*64+qrow]=v.y+rrb[n*DH+d+1];
            qaT[(d+2)*64+qrow]=v.z+rwb[n*DH+d+2]; qbT[(d+2)*64+qrow]=v.z+rrb[n*DH+d+2];
            qaT[(d+3)*64+qrow]=v.w+rwb[n*DH+d+3]; qbT[(d+3)*64+qrow]=v.w+rrb[n*DH+d+3];
        }
    }

    float mrow[4], lrow[4], o[4][4];
    #pragma unroll
    for (int a = 0; a < 4; a++) {
        mrow[a] = -1e30f; lrow[a] = 0.f;
        #pragma unroll
        for (int c = 0; c < 4; c++) o[a][c] = 0.f;
    }

    const float fscale = 0.18033688011112042f;
    const int ntiles = (i0>>6) + 17;
    const int rb4 = ((tx - ty)<<2) + 60;

    for (int tile = 0; tile < ntiles; tile++) {
        const int j0 = tile<<6;
        __syncthreads();
        {
            int jc = lane + ((w>>2)<<5); int d0 = (w&3)<<4;
            const float* kp = Kb + (size_t)(j0+jc)*DH + d0;
            #pragma unroll
            for (int u = 0; u < 4; u++) {
                float4 v = *(const float4*)(kp + 4*u); int d = d0 + 4*u;
                ktT[(d+0)*64+jc]=v.x; ktT[(d+1)*64+jc]=v.y;
                ktT[(d+2)*64+jc]=v.z; ktT[(d+3)*64+jc]=v.w;
            }
        }
        {
            int jc = t>>2; int d0 = (t&3)<<4;
            const float* vp = Vb + (size_t)(j0+jc)*DH + d0;
            #pragma unroll
            for (int u = 0; u < 4; u++)
                *(float4*)&vt[jc*64 + d0 + 4*u] = *(const float4*)(vp + 4*u);
        }
        {
            int rr = lane + ((w>>1)<<5); int d0 = (w&1)<<5;
            int mg = j0 + 960 - i0 + rr;
            #pragma unroll
            for (int u = 0; u < 8; u++) {
                int d = d0 + 4*u;
                float4 v = make_float4(0.f,0.f,0.f,0.f);
                if (mg < KLENN) v = *(const float4*)(Rb + (size_t)mg*DH + d);
                rtT[(d+0)*128+rr]=v.x; rtT[(d+1)*128+rr]=v.y;
                rtT[(d+2)*128+rr]=v.z; rtT[(d+3)*128+rr]=v.w;
            }
        }
        __syncthreads();

        float acc[4][4];
        #pragma unroll
        for (int a = 0; a < 4; a++) {
            #pragma unroll
            for (int c = 0; c < 4; c++) acc[a][c] = 0.f;
        }
        #pragma unroll 8
        for (int d = 0; d < 64; d++) {
            float4 qa4 = *(const float4*)&qaT[d*64 + (ty<<2)];
            float4 qb4 = *(const float4*)&qbT[d*64 + (ty<<2)];
            float4 kk4 = *(const float4*)&ktT[d*64 + (tx<<2)];
            float4 r04 = *(const float4*)&rtT[d*128 + rb4];
            float4 r14 = *(const float4*)&rtT[d*128 + rb4 + 4];
            float qaa[4]={qa4.x,qa4.y,qa4.z,qa4.w};
            float qbb[4]={qb4.x,qb4.y,qb4.z,qb4.w};
            float kkk[4]={kk4.x,kk4.y,kk4.z,kk4.w};
            float rr7[7]={r04.x,r04.y,r04.z,r04.w,r14.x,r14.y,r14.z};
            #pragma unroll
            for (int a = 0; a < 4; a++) {
                #pragma unroll
                for (int c = 0; c < 4; c++)
                    acc[a][c] += qaa[a]*kkk[c] + qbb[a]*rr7[c-a+3];
            }
        }

        #pragma unroll
        for (int a = 0; a < 4; a++) {
            const int iq = i0 + (ty<<2) + a;
            float s[4];
            #pragma unroll
            for (int c = 0; c < 4; c++) {
                int jk = j0 + (tx<<2) + c;
                s[c] = (jk > iq + MLEN) ? -1e30f : acc[a][c]*fscale;
            }
            float tm = fmaxf(fmaxf(s[0],s[1]), fmaxf(s[2],s[3]));
            tm = fmaxf(tm, __shfl_xor_sync(0xffffffffu, tm, 8));
            tm = fmaxf(tm, __shfl_xor_sync(0xffffffffu, tm, 4));
            tm = fmaxf(tm, __shfl_xor_sync(0xffffffffu, tm, 2));
            tm = fmaxf(tm, __shfl_xor_sync(0xffffffffu, tm, 1));
            float mn = fmaxf(mrow[a], tm);
            float cf = ex2(mrow[a] - mn);
            mrow[a] = mn;
            float p0=ex2(s[0]-mn), p1=ex2(s[1]-mn), p2=ex2(s[2]-mn), p3=ex2(s[3]-mn);
            lrow[a] = lrow[a]*cf + (p0+p1+p2+p3);
            #pragma unroll
            for (int c = 0; c < 4; c++) o[a][c] *= cf;
            *(float4*)&ps[((ty<<2)+a)*68 + (tx<<2)] = make_float4(p0,p1,p2,p3);
        }
        __syncthreads();

        #pragma unroll 4
        for (int j = 0; j < 64; j++) {
            float4 v4 = *(const float4*)&vt[j*64 + (tx<<2)];
            #pragma unroll
            for (int a = 0; a < 4; a++) {
                float pa = ps[((ty<<2)+a)*68 + j];
                o[a][0] += pa*v4.x; o[a][1] += pa*v4.y;
                o[a][2] += pa*v4.z; o[a][3] += pa*v4.w;
            }
        }
    }

    #pragma unroll
    for (int a = 0; a < 4; a++) {
        float lt = lrow[a];
        lt += __shfl_xor_sync(0xffffffffu, lt, 8);
        lt += __shfl_xor_sync(0xffffffffu, lt, 4);
        lt += __shfl_xor_sync(0xffffffffu, lt, 2);
        lt += __shfl_xor_sync(0xffffffffu, lt, 1);
        float inv = 1.f / lt;
        float4 v = make_float4(o[a][0]*inv, o[a][1]*inv, o[a][2]*inv, o[a][3]*inv);
        size_t row = (size_t)(i0 + (ty<<2) + a)*BATCH + b;
        *(float4*)&g_AV[row*DM + n*DH + (tx<<2)] = v;
    }
}

// LayerNorm over g_O rows -> d_out
__global__ __launch_bounds__(256)
void k_ln(const float* __restrict__ gamma, const float* __restrict__ beta,
          float* __restrict__ out)
{
    __shared__ float red[16];
    const int t = threadIdx.x;
    const size_t row = blockIdx.x;
    float4 x = *(const float4*)&g_O[row*DM + t*4];
    float s = x.x + x.y + x.z + x.w;
    float ss = x.x*x.x + x.y*x.y + x.z*x.z + x.w*x.w;
    #pragma unroll
    for (int m = 16; m > 0; m >>= 1) {
        s  += __shfl_xor_sync(0xffffffffu, s, m);
        ss += __shfl_xor_sync(0xffffffffu, ss, m);
    }
    if ((t&31) == 0) { red[t>>5] = s; red[8 + (t>>5)] = ss; }
    __syncthreads();
    if (t < 8) {
        float a = red[t], bsum = red[8+t];
        #pragma unroll
        for (int m = 4; m > 0; m >>= 1) {
            a    += __shfl_xor_sync(0xffu, a, m);
            bsum += __shfl_xor_sync(0xffu, bsum, m);
        }
        if (t == 0) { red[0] = a; red[8] = bsum; }
    }
    __syncthreads();
    float mu = red[0] * (1.f/DM);
    float var = red[8] * (1.f/DM) - mu*mu;
    float rs = rsqrtf(var + 1e-5f);
    float4 g = *(const float4*)&gamma[t*4];
    float4 be = *(const float4*)&beta[t*4];
    float4 y;
    y.x = (x.x-mu)*rs*g.x + be.x;
    y.y = (x.y-mu)*rs*g.y + be.y;
    y.z = (x.z-mu)*rs*g.z + be.z;
    y.w = (x.w-mu)*rs*g.w + be.w;
    *(float4*)&out[row*DM + t*4] = y;
}

extern "C" void kernel_launch(void* const* d_in, const int* in_sizes, int n_in,
                              void* d_out, int out_size)
{
    const float* content = (const float*)d_in[0];
    const float* rel_pos = (const float*)d_in[1];
    const float* mems    = (const float*)d_in[2];
    const float* rwb     = (const float*)d_in[3];
    const float* rrb     = (const float*)d_in[4];
    const float* Wqkv    = (const float*)d_in[5];
    const float* Wr      = (const float*)d_in[6];
    const float* Wo      = (const float*)d_in[7];
    const float* gamma   = (const float*)d_in[8];
    const float* beta    = (const float*)d_in[9];
    float* out = (float*)d_out;

    cudaFuncSetAttribute(k_attn,  cudaFuncAttributeMaxDynamicSharedMemorySize, SMEM_ATTN);
    cudaFuncSetAttribute(k_qkv,   cudaFuncAttributeMaxDynamicSharedMemorySize, SMEM_GEMM);
    cudaFuncSetAttribute(k_rproj, cudaFuncAttributeMaxDynamicSharedMemorySize, SMEM_GEMM);
    cudaFuncSetAttribute(k_out,   cudaFuncAttributeMaxDynamicSharedMemorySize, SMEM_GEMM);

    __nv_bfloat16 *Ah, *Al, *W3h, *W3l, *Rph, *Rpl, *Wrh, *Wrl, *Woh, *Wol, *AVh, *AVl;
    float *AV;
    cudaGetSymbolAddress((void**)&Ah,  g_Ah);
    cudaGetSymbolAddress((void**)&Al,  g_Al);
    cudaGetSymbolAddress((void**)&W3h, g_W3h);
    cudaGetSymbolAddress((void**)&W3l, g_W3l);
    cudaGetSymbolAddress((void**)&Rph, g_Rph);
    cudaGetSymbolAddress((void**)&Rpl, g_Rpl);
    cudaGetSymbolAddress((void**)&Wrh, g_Wrh);
    cudaGetSymbolAddress((void**)&Wrl, g_Wrl);
    cudaGetSymbolAddress((void**)&Woh, g_Woh);
    cudaGetSymbolAddress((void**)&Wol, g_Wol);
    cudaGetSymbolAddress((void**)&AVh, g_AVh);
    cudaGetSymbolAddress((void**)&AVl, g_AVl);
    cudaGetSymbolAddress((void**)&AV,  g_AV);

    const int MB = 4096*DM/4;
    k_splitb<<<(MB+255)/256, 256>>>(mems,    Ah,            Al,            MB);
    k_splitb<<<(MB+255)/256, 256>>>(content, Ah + 4096*DM,  Al + 4096*DM,  MB);
    k_splitb<<<(DM*3072/4+255)/256, 256>>>(Wqkv,    W3h, W3l, DM*3072/4);
    k_splitb<<<(KLENN*DM/4+255)/256, 256>>>(rel_pos, Rph, Rpl, KLENN*DM/4);
    k_splitb<<<(DM*DM/4+255)/256, 256>>>(Wr, Wrh, Wrl, DM*DM/4);
    k_splitb<<<(DM*DM/4+255)/256, 256>>>(Wo, Woh, Wol, DM*DM/4);

    k_qkv  <<<dim3(24, 64), 256, SMEM_GEMM>>>();
    k_rproj<<<dim3(8, 16),  256, SMEM_GEMM>>>();
    k_attn <<<dim3(QLEN/64, NH, BATCH), 256, SMEM_ATTN>>>(rwb, rrb);
    k_splitb<<<(MB+255)/256, 256>>>(AV, AVh, AVl, MB);
    k_out  <<<dim3(8, 32),  256, SMEM_GEMM>>>(content);
    k_ln   <<<QLEN*BATCH, 256>>>(gamma, beta, out);
}

// round 9
// speedup vs baseline: 3.2644x; 2.0973x over previous
#include <cuda_runtime.h>
#include <cuda_bf16.h>
#include <cuda_fp16.h>
#include <cstdint>

#define QLEN  1024
#define MLEN  1024
#define KLENN 2048
#define BATCH 4
#define NH    16
#define DH    64
#define DM    1024

// fp32 scratch
__device__ float g_Q[BATCH*NH*QLEN*DH];
__device__ float g_K[BATCH*NH*KLENN*DH];
__device__ float g_V[BATCH*NH*KLENN*DH];
__device__ float g_R[NH*KLENN*DH];
__device__ float g_AV[QLEN*BATCH*DM];
__device__ float g_O[QLEN*BATCH*DM];
// bf16 hi/lo planes (GEMMs)
__device__ __nv_bfloat16 g_Ah[8192*DM],  g_Al[8192*DM];
__device__ __nv_bfloat16 g_W3h[DM*3072], g_W3l[DM*3072];
__device__ __nv_bfloat16 g_Rph[KLENN*DM],g_Rpl[KLENN*DM];
__device__ __nv_bfloat16 g_Wrh[DM*DM],   g_Wrl[DM*DM];
__device__ __nv_bfloat16 g_Woh[DM*DM],   g_Wol[DM*DM];
__device__ __nv_bfloat16 g_AVh[4096*DM], g_AVl[4096*DM];
// fp16 attention operands
__device__ __half g_Qah[BATCH*NH*QLEN*DH];
__device__ __half g_Qbh[BATCH*NH*QLEN*DH];
__device__ __half g_Kh[BATCH*NH*KLENN*DH];
__device__ __half g_Vh[BATCH*NH*KLENN*DH];
__device__ __half g_Rh[NH*KLENN*DH];

__device__ __forceinline__ float ex2(float x) {
    float y; asm("ex2.approx.ftz.f32 %0, %1;" : "=f"(y) : "f"(x)); return y;
}

// ---------------------------------------------------------------------------
// bf16 split kernel (GEMM precision): hi = bf16(x), lo = bf16(x - hi)
// ---------------------------------------------------------------------------
__global__ __launch_bounds__(256)
void k_splitb(const float* __restrict__ src, __nv_bfloat16* __restrict__ hi,
              __nv_bfloat16* __restrict__ lo, int n4)
{
    int i = blockIdx.x*256 + threadIdx.x;
    if (i < n4) {
        float4 v = ((const float4*)src)[i];
        float f[4] = {v.x, v.y, v.z, v.w};
        uint32_t hp[2], lp[2];
        #pragma unroll
        for (int p = 0; p < 2; p++) {
            __nv_bfloat16 h0 = __float2bfloat16(f[2*p]);
            __nv_bfloat16 h1 = __float2bfloat16(f[2*p+1]);
            __nv_bfloat16 l0 = __float2bfloat16(f[2*p]   - __bfloat162float(h0));
            __nv_bfloat16 l1 = __float2bfloat16(f[2*p+1] - __bfloat162float(h1));
            hp[p] = (uint32_t)__bfloat16_as_ushort(h0) | ((uint32_t)__bfloat16_as_ushort(h1)<<16);
            lp[p] = (uint32_t)__bfloat16_as_ushort(l0) | ((uint32_t)__bfloat16_as_ushort(l1)<<16);
        }
        ((uint2*)hi)[i] = make_uint2(hp[0], hp[1]);
        ((uint2*)lo)[i] = make_uint2(lp[0], lp[1]);
    }
}

// fp32 -> fp16 cast (attention operands)
__global__ __launch_bounds__(256)
void k_tohalf(const float* __restrict__ src, __half* __restrict__ dst, int n4)
{
    int i = blockIdx.x*256 + threadIdx.x;
    if (i < n4) {
        float4 v = ((const float4*)src)[i];
        __half2 h01 = __floats2half2_rn(v.x, v.y);
        __half2 h23 = __floats2half2_rn(v.z, v.w);
        ((uint2*)dst)[i] = make_uint2(*(uint32_t*)&h01, *(uint32_t*)&h23);
    }
}

// Q + biases -> fp16 Qa/Qb planes. g_Q layout ((b*16+n)*1024+q)*64+d
__global__ __launch_bounds__(256)
void k_qprep(const float* __restrict__ rwb, const float* __restrict__ rrb)
{
    int i = blockIdx.x*256 + threadIdx.x;     // over 1M float4
    if (i >= BATCH*NH*QLEN*DH/4) return;
    float4 v = ((const float4*)g_Q)[i];
    int d = (i & 15) * 4;
    int n = (i >> 14) & 15;
    float4 wa = *(const float4*)&rwb[n*DH + d];
    float4 wb = *(const float4*)&rrb[n*DH + d];
    __half2 a01 = __floats2half2_rn(v.x+wa.x, v.y+wa.y);
    __half2 a23 = __floats2half2_rn(v.z+wa.z, v.w+wa.w);
    __half2 b01 = __floats2half2_rn(v.x+wb.x, v.y+wb.y);
    __half2 b23 = __floats2half2_rn(v.z+wb.z, v.w+wb.w);
    ((uint2*)g_Qah)[i] = make_uint2(*(uint32_t*)&a01, *(uint32_t*)&a23);
    ((uint2*)g_Qbh)[i] = make_uint2(*(uint32_t*)&b01, *(uint32_t*)&b23);
}

// ---------------------------------------------------------------------------
// MMA primitives
// ---------------------------------------------------------------------------
__device__ __forceinline__ void ldsm4(uint32_t (&r)[4], uint32_t addr) {
    asm volatile("ldmatrix.sync.aligned.m8n8.x4.shared.b16 {%0,%1,%2,%3}, [%4];"
        : "=r"(r[0]), "=r"(r[1]), "=r"(r[2]), "=r"(r[3]) : "r"(addr));
}
__device__ __forceinline__ void ldsm4t(uint32_t (&r)[4], uint32_t addr) {
    asm volatile("ldmatrix.sync.aligned.m8n8.x4.trans.shared.b16 {%0,%1,%2,%3}, [%4];"
        : "=r"(r[0]), "=r"(r[1]), "=r"(r[2]), "=r"(r[3]) : "r"(addr));
}
__device__ __forceinline__ void mma16b(float (&c)[4], const uint32_t (&a)[4],
                                       uint32_t b0, uint32_t b1) {
    asm volatile(
        "mma.sync.aligned.m16n8k16.row.col.f32.bf16.bf16.f32 "
        "{%0,%1,%2,%3},{%4,%5,%6,%7},{%8,%9},{%0,%1,%2,%3};"
        : "+f"(c[0]), "+f"(c[1]), "+f"(c[2]), "+f"(c[3])
        : "r"(a[0]), "r"(a[1]), "r"(a[2]), "r"(a[3]), "r"(b0), "r"(b1));
}
__device__ __forceinline__ void mma16h(float (&c)[4], const uint32_t (&a)[4],
                                       uint32_t b0, uint32_t b1) {
    asm volatile(
        "mma.sync.aligned.m16n8k16.row.col.f32.f16.f16.f32 "
        "{%0,%1,%2,%3},{%4,%5,%6,%7},{%8,%9},{%0,%1,%2,%3};"
        : "+f"(c[0]), "+f"(c[1]), "+f"(c[2]), "+f"(c[3])
        : "r"(a[0]), "r"(a[1]), "r"(a[2]), "r"(a[3]), "r"(b0), "r"(b1));
}
__device__ __forceinline__ void cpa16(uint32_t dst, const void* src) {
    asm volatile("cp.async.cg.shared.global [%0], [%1], 16;" :: "r"(dst), "l"(src));
}
__device__ __forceinline__ void cpa16z(uint32_t dst, const void* src, int nbytes) {
    asm volatile("cp.async.cg.shared.global [%0], [%1], 16, %2;"
                 :: "r"(dst), "l"(src), "r"(nbytes));
}

// ---------------------------------------------------------------------------
// bf16-split GEMM (unchanged from round 7)
// ---------------------------------------------------------------------------
#define KS 32
#define A_PAD 40
#define B_PAD 136
#define A_PLANE (128*A_PAD)
#define A_BUF   (2*A_PLANE)
#define B_PLANE (KS*B_PAD)
#define B_BUF   (2*B_PLANE)
#define BUF_ELEMS (A_BUF + B_BUF)
#define SMEM_GEMM (2*BUF_ELEMS*2)

__device__ __forceinline__ void cta_load(
    uint32_t sb, int buf,
    const __nv_bfloat16* __restrict__ Ah, const __nv_bfloat16* __restrict__ Al, size_t m0,
    const __nv_bfloat16* __restrict__ Bh, const __nv_bfloat16* __restrict__ Bl,
    int ldb, int n0, int kt, int t)
{
    uint32_t bo = sb + (uint32_t)buf * (BUF_ELEMS*2);
    #pragma unroll
    for (int i = 0; i < 4; i++) {
        int c = t + 256*i;
        int p = c >> 9, rc = c & 511;
        int row = rc >> 2, seg = rc & 3;
        const __nv_bfloat16* src = (p ? Al : Ah) + (m0 + row)*DM + kt + seg*8;
        cpa16(bo + (uint32_t)(p*A_PLANE + row*A_PAD + seg*8)*2, src);
    }
    #pragma unroll
    for (int i = 0; i < 4; i++) {
        int c = t + 256*i;
        int p = c >> 9, rc = c & 511;
        int row = rc >> 4, seg = rc & 15;
        const __nv_bfloat16* src = (p ? Bl : Bh) + (size_t)(kt + row)*ldb + n0 + seg*8;
        cpa16(bo + (uint32_t)(A_BUF*2 + (p*B_PLANE + row*B_PAD + seg*8)*2), src);
    }
}

__device__ __forceinline__ void gemm_bf16(
    const __nv_bfloat16* __restrict__ Ah, const __nv_bfloat16* __restrict__ Al, size_t m0,
    const __nv_bfloat16* __restrict__ Bh, const __nv_bfloat16* __restrict__ Bl,
    int ldb, int n0, float (&C)[4][4][4], char* smem, int t)
{
    uint32_t sb = (uint32_t)__cvta_generic_to_shared(smem);
    const int lane = t&31, w = t>>5, wm = w>>2, wn = w&3;
    const uint32_t aBase = (uint32_t)(((wm*64 + (lane&15))*A_PAD + ((lane>>4)<<3))*2);
    const uint32_t bBase = (uint32_t)(A_BUF*2 + (((lane&15))*B_PAD + wn*32 + ((lane>>4)<<3))*2);

    cta_load(sb, 0, Ah, Al, m0, Bh, Bl, ldb, n0, 0, t);
    asm volatile("cp.async.commit_group;");

    for (int it = 0; it < DM/KS; ++it) {
        int buf = it & 1;
        if (it + 1 < DM/KS) {
            cta_load(sb, 1-buf, Ah, Al, m0, Bh, Bl, ldb, n0, (it+1)*KS, t);
            asm volatile("cp.async.commit_group;");
            asm volatile("cp.async.wait_group 1;");
        } else {
            asm volatile("cp.async.wait_group 0;");
        }
        __syncthreads();

        uint32_t bo = sb + (uint32_t)buf*(BUF_ELEMS*2);
        #pragma unroll
        for (int c16 = 0; c16 < 2; c16++) {
            uint32_t bb = bo + bBase + (uint32_t)(c16*16*B_PAD*2);
            uint32_t bH0[4], bS0[4], bH1[4], bS1[4];
            ldsm4t(bH0, bb);
            ldsm4t(bS0, bb + B_PLANE*2);
            ldsm4t(bH1, bb + 32);
            ldsm4t(bS1, bb + 32 + B_PLANE*2);
            #pragma unroll
            for (int mt = 0; mt < 4; mt++) {
                uint32_t ab = bo + aBase + (uint32_t)(mt*16*A_PAD*2 + c16*32);
                uint32_t aH[4], aS[4];
                ldsm4(aH, ab);
                ldsm4(aS, ab + A_PLANE*2);
                mma16b(C[mt][0], aH, bH0[0], bH0[1]);
                mma16b(C[mt][0], aH, bS0[0], bS0[1]);
                mma16b(C[mt][0], aS, bH0[0], bH0[1]);
                mma16b(C[mt][1], aH, bH0[2], bH0[3]);
                mma16b(C[mt][1], aH, bS0[2], bS0[3]);
                mma16b(C[mt][1], aS, bH0[2], bH0[3]);
                mma16b(C[mt][2], aH, bH1[0], bH1[1]);
                mma16b(C[mt][2], aH, bS1[0], bS1[1]);
                mma16b(C[mt][2], aS, bH1[0], bH1[1]);
                mma16b(C[mt][3], aH, bH1[2], bH1[3]);
                mma16b(C[mt][3], aH, bS1[2], bS1[3]);
                mma16b(C[mt][3], aS, bH1[2], bH1[3]);
            }
        }
        __syncthreads();
    }
}

__global__ __launch_bounds__(256)
void k_qkv()
{
    extern __shared__ char smg[];
    const int t = threadIdx.x, n0 = blockIdx.x<<7, m0 = blockIdx.y<<7;
    const int lane = t&31, w = t>>5, wm = w>>2, wn = w&3;
    const int tig = lane&3, grp = lane>>2;
    float C[4][4][4];
    #pragma unroll
    for (int i = 0; i < 4; i++) {
        #pragma unroll
        for (int j = 0; j < 4; j++) {
            #pragma unroll
            for (int k = 0; k < 4; k++) C[i][j][k] = 0.f;
        }
    }
    gemm_bf16(g_Ah, g_Al, (size_t)m0, g_W3h, g_W3l, 3072, n0, C, smg, t);

    #pragma unroll
    for (int mt = 0; mt < 4; mt++) {
        #pragma unroll
        for (int h = 0; h < 2; h++) {
            int m = m0 + wm*64 + mt*16 + grp + 8*h;
            int row = m >> 2, bb = m & 3;
            #pragma unroll
            for (int nt = 0; nt < 4; nt++) {
                int col = n0 + wn*32 + nt*8 + 2*tig;
                int sec = col >> 10, nn = (col>>6)&15, dd = col & 63;
                float2 v = make_float2(C[mt][nt][2*h], C[mt][nt][2*h+1]);
                if (sec == 0) {
                    if (row >= MLEN)
                        *(float2*)&g_Q[(((size_t)bb*NH+nn)*QLEN + (row-MLEN))*DH + dd] = v;
                } else if (sec == 1) {
                    *(float2*)&g_K[(((size_t)bb*NH+nn)*KLENN + row)*DH + dd] = v;
                } else {
                    *(float2*)&g_V[(((size_t)bb*NH+nn)*KLENN + row)*DH + dd] = v;
                }
            }
        }
    }
}

__global__ __launch_bounds__(256)
void k_rproj()
{
    extern __shared__ char smg[];
    const int t = threadIdx.x, n0 = blockIdx.x<<7, m0 = blockIdx.y<<7;
    const int lane = t&31, w = t>>5, wm = w>>2, wn = w&3;
    const int tig = lane&3, grp = lane>>2;
    float C[4][4][4];
    #pragma unroll
    for (int i = 0; i < 4; i++) {
        #pragma unroll
        for (int j = 0; j < 4; j++) {
            #pragma unroll
            for (int k = 0; k < 4; k++) C[i][j][k] = 0.f;
        }
    }
    gemm_bf16(g_Rph, g_Rpl, (size_t)m0, g_Wrh, g_Wrl, DM, n0, C, smg, t);

    #pragma unroll
    for (int mt = 0; mt < 4; mt++) {
        #pragma unroll
        for (int h = 0; h < 2; h++) {
            int m = m0 + wm*64 + mt*16 + grp + 8*h;
            #pragma unroll
            for (int nt = 0; nt < 4; nt++) {
                int col = n0 + wn*32 + nt*8 + 2*tig;
                int nn = col >> 6, dd = col & 63;
                float2 v = make_float2(C[mt][nt][2*h], C[mt][nt][2*h+1]);
                *(float2*)&g_R[((size_t)nn*KLENN + m)*DH + dd] = v;
            }
        }
    }
}

__global__ __launch_bounds__(256)
void k_out(const float* __restrict__ content)
{
    extern __shared__ char smg[];
    const int t = threadIdx.x, n0 = blockIdx.x<<7, m0 = blockIdx.y<<7;
    const int lane = t&31, w = t>>5, wm = w>>2, wn = w&3;
    const int tig = lane&3, grp = lane>>2;
    float C[4][4][4];
    #pragma unroll
    for (int i = 0; i < 4; i++) {
        #pragma unroll
        for (int j = 0; j < 4; j++) {
            #pragma unroll
            for (int k = 0; k < 4; k++) C[i][j][k] = 0.f;
        }
    }
    gemm_bf16(g_AVh, g_AVl, (size_t)m0, g_Woh, g_Wol, DM, n0, C, smg, t);

    #pragma unroll
    for (int mt = 0; mt < 4; mt++) {
        #pragma unroll
        for (int h = 0; h < 2; h++) {
            size_t m = m0 + wm*64 + mt*16 + grp + 8*h;
            #pragma unroll
            for (int nt = 0; nt < 4; nt++) {
                int col = n0 + wn*32 + nt*8 + 2*tig;
                float2 c4 = *(const float2*)(content + m*DM + col);
                float2 v = make_float2(C[mt][nt][2*h] + c4.x, C[mt][nt][2*h+1] + c4.y);
                *(float2*)&g_O[m*DM + col] = v;
            }
        }
    }
}

// ---------------------------------------------------------------------------
// MMA flash attention with XL rel-shift. 64 q-rows/CTA, 256 thr.
// S1 = Qa K^T (64x64), S2 = Qb Rwin^T (64x128); gather S2[il][jc-il+63].
// ---------------------------------------------------------------------------
#define OQA 0
#define OQB 9216
#define OKT 18432
#define OVT 27648
#define ORT 36864
#define OS1 55296
#define OS2 72704
#define OPS 106496
#define OCF 115712
#define OLI 115968
#define SMEM_ATTN 116224

__global__ __launch_bounds__(256)
void k_attn()
{
    extern __shared__ char sm[];
    uint32_t sb = (uint32_t)__cvta_generic_to_shared(sm);
    float* sS1 = (float*)(sm + OS1);   // [64][68]
    float* sS2 = (float*)(sm + OS2);   // [64][132]
    __half* pS = (__half*)(sm + OPS);  // [64][72]
    float* cfs = (float*)(sm + OCF);
    float* lis = (float*)(sm + OLI);

    const int t = threadIdx.x, lane = t&31, w = t>>5;
    const int tx = t&15, ty = t>>4;
    const int wm = w&3, wn = w>>2;
    const int tig = lane&3, grp = lane>>2;
    const int i0 = blockIdx.x<<6, n = blockIdx.y, b = blockIdx.z;

    const __half* Qag = g_Qah + ((size_t)(b*NH+n)*QLEN + i0)*DH;
    const __half* Qbg = g_Qbh + ((size_t)(b*NH+n)*QLEN + i0)*DH;
    const __half* Kg  = g_Kh  + (size_t)(b*NH+n)*KLENN*DH;
    const __half* Vg  = g_Vh  + (size_t)(b*NH+n)*KLENN*DH;
    const __half* Rg  = g_Rh  + (size_t)n*KLENN*DH;

    // Q tiles -> smem (once)
    #pragma unroll
    for (int i = 0; i < 4; i++) {
        int c = t + 256*i;
        int which = c >> 9, rc = c & 511;
        int row = rc >> 3, seg = rc & 7;
        const __half* src = (which ? Qbg : Qag) + row*DH + seg*8;
        cpa16(sb + (which ? OQB : OQA) + (uint32_t)(row*72 + seg*8)*2, src);
    }
    asm volatile("cp.async.commit_group;");
    asm volatile("cp.async.wait_group 0;");
    __syncthreads();

    // Qa/Qb A-fragments (persist)
    uint32_t aQa[4][4], aQb[4][4];
    #pragma unroll
    for (int ks = 0; ks < 4; ks++) {
        uint32_t off = (uint32_t)(((wm*16 + (lane&15))*72 + ks*16 + ((lane>>4)<<3))*2);
        ldsm4(aQa[ks], sb + OQA + off);
        ldsm4(aQb[ks], sb + OQB + off);
    }

    float mrow[4], lrow[4], oC[4][4];
    #pragma unroll
    for (int a = 0; a < 4; a++) { mrow[a] = -1e30f; lrow[a] = 0.f; }
    #pragma unroll
    for (int nb = 0; nb < 4; nb++) {
        #pragma unroll
        for (int k = 0; k < 4; k++) oC[nb][k] = 0.f;
    }

    const float fscale = 0.18033688011112042f;  // (1/8)*log2(e)
    const int ntiles = (i0>>6) + 17;

    for (int tile = 0; tile < ntiles; tile++) {
        const int j0 = tile<<6;
        __syncthreads();
        // load K, V, R(window) fp16 via cp.async
        #pragma unroll
        for (int i = 0; i < 8; i++) {
            int c = t + 256*i;
            if (c < 512) {
                int row = c >> 3, seg = c & 7;
                cpa16(sb + OKT + (uint32_t)(row*72 + seg*8)*2, Kg + (size_t)(j0+row)*DH + seg*8);
            } else if (c < 1024) {
                int rc = c - 512, row = rc >> 3, seg = rc & 7;
                cpa16(sb + OVT + (uint32_t)(row*72 + seg*8)*2, Vg + (size_t)(j0+row)*DH + seg*8);
            } else {
                int rc = c - 1024, row = rc >> 3, seg = rc & 7;
                int mg = j0 + 960 - i0 + row;
                int ok = (mg < KLENN) ? 16 : 0;
                if (mg >= KLENN) mg = KLENN - 1;
                cpa16z(sb + ORT + (uint32_t)(row*72 + seg*8)*2, Rg + (size_t)mg*DH + seg*8, ok);
            }
        }
        asm volatile("cp.async.commit_group;");
        asm volatile("cp.async.wait_group 0;");
        __syncthreads();

        // S-MMA: 24 n-blocks of 8 across wn halves (0..7 = K, 8..23 = R)
        float sC[12][4];
        #pragma unroll
        for (int p = 0; p < 12; p++) {
            #pragma unroll
            for (int k = 0; k < 4; k++) sC[p][k] = 0.f;
        }
        #pragma unroll
        for (int ks = 0; ks < 4; ks++) {
            uint32_t bf[6][4];
            #pragma unroll
            for (int p = 0; p < 6; p++) {
                int blk = wn*12 + 2*p;
                uint32_t base = (blk < 8) ? (sb + OKT) : (sb + ORT);
                int nrow = (blk < 8) ? blk*8 : (blk-8)*8;
                uint32_t addr = base + (uint32_t)(((nrow + (lane&7) + ((lane>>4)<<3))*72
                                 + ks*16 + (((lane>>3)&1)<<3))*2);
                ldsm4(bf[p], addr);
            }
            #pragma unroll
            for (int p = 0; p < 6; p++) {
                int blk = wn*12 + 2*p;
                if (blk < 8) { mma16h(sC[2*p], aQa[ks], bf[p][0], bf[p][1]); }
                else         { mma16h(sC[2*p], aQb[ks], bf[p][0], bf[p][1]); }
                if (blk+1 < 8) { mma16h(sC[2*p+1], aQa[ks], bf[p][2], bf[p][3]); }
                else           { mma16h(sC[2*p+1], aQb[ks], bf[p][2], bf[p][3]); }
            }
        }
        // spill S to smem
        #pragma unroll
        for (int p = 0; p < 12; p++) {
            int blk = wn*12 + p;
            int r0 = wm*16 + grp;
            if (blk < 8) {
                int col = blk*8 + 2*tig;
                *(float2*)&sS1[r0*68 + col]     = make_float2(sC[p][0], sC[p][1]);
                *(float2*)&sS1[(r0+8)*68 + col] = make_float2(sC[p][2], sC[p][3]);
            } else {
                int col = (blk-8)*8 + 2*tig;
                *(float2*)&sS2[r0*132 + col]     = make_float2(sC[p][0], sC[p][1]);
                *(float2*)&sS2[(r0+8)*132 + col] = make_float2(sC[p][2], sC[p][3]);
            }
        }
        __syncthreads();

        // softmax (scalar, 16x16 thread grid)
        #pragma unroll
        for (int a = 0; a < 4; a++) {
            const int il = ty*4 + a;
            const int iq = i0 + il;
            float4 s1 = *(const float4*)&sS1[il*68 + tx*4];
            int gb = tx*4 - il + 63;
            float s[4];
            s[0] = s1.x + sS2[il*132 + gb];
            s[1] = s1.y + sS2[il*132 + gb+1];
            s[2] = s1.z + sS2[il*132 + gb+2];
            s[3] = s1.w + sS2[il*132 + gb+3];
            #pragma unroll
            for (int c = 0; c < 4; c++) {
                int jk = j0 + tx*4 + c;
                s[c] = (jk > iq + MLEN) ? -1e30f : s[c]*fscale;
            }
            float tm = fmaxf(fmaxf(s[0],s[1]), fmaxf(s[2],s[3]));
            tm = fmaxf(tm, __shfl_xor_sync(0xffffffffu, tm, 8));
            tm = fmaxf(tm, __shfl_xor_sync(0xffffffffu, tm, 4));
            tm = fmaxf(tm, __shfl_xor_sync(0xffffffffu, tm, 2));
            tm = fmaxf(tm, __shfl_xor_sync(0xffffffffu, tm, 1));
            float mn = fmaxf(mrow[a], tm);
            float cf = ex2(mrow[a] - mn);
            mrow[a] = mn;
            float p0=ex2(s[0]-mn), p1=ex2(s[1]-mn), p2=ex2(s[2]-mn), p3=ex2(s[3]-mn);
            lrow[a] = lrow[a]*cf + (p0+p1+p2+p3);
            __half2 h01 = __floats2half2_rn(p0, p1);
            __half2 h23 = __floats2half2_rn(p2, p3);
            *(uint2*)&pS[il*72 + tx*4] = make_uint2(*(uint32_t*)&h01, *(uint32_t*)&h23);
            if (tx == 0) cfs[il] = cf;
        }
        __syncthreads();

        // PV: rescale O, accumulate P*V
        {
            int r0 = wm*16 + grp;
            float cf0 = cfs[r0], cf1 = cfs[r0+8];
            #pragma unroll
            for (int nb = 0; nb < 4; nb++) {
                oC[nb][0] *= cf0; oC[nb][1] *= cf0;
                oC[nb][2] *= cf1; oC[nb][3] *= cf1;
            }
        }
        #pragma unroll
        for (int ks = 0; ks < 4; ks++) {
            uint32_t aP[4];
            ldsm4(aP, sb + OPS + (uint32_t)(((wm*16 + (lane&15))*72 + ks*16 + ((lane>>4)<<3))*2));
            uint32_t bv0[4], bv1[4];
            uint32_t vb = sb + OVT + (uint32_t)(((ks*16 + (lane&15))*72 + wn*32 + ((lane>>4)<<3))*2);
            ldsm4t(bv0, vb);
            ldsm4t(bv1, vb + 32);
            mma16h(oC[0], aP, bv0[0], bv0[1]);
            mma16h(oC[1], aP, bv0[2], bv0[3]);
            mma16h(oC[2], aP, bv1[0], bv1[1]);
            mma16h(oC[3], aP, bv1[2], bv1[3]);
        }
    }

    // final normalize + store
    #pragma unroll
    for (int a = 0; a < 4; a++) {
        float lt = lrow[a];
        lt += __shfl_xor_sync(0xffffffffu, lt, 8);
        lt += __shfl_xor_sync(0xffffffffu, lt, 4);
        lt += __shfl_xor_sync(0xffffffffu, lt, 2);
        lt += __shfl_xor_sync(0xffffffffu, lt, 1);
        if (tx == 0) lis[ty*4+a] = 1.f / lt;
    }
    __syncthreads();
    {
        int r0 = wm*16 + grp;
        float li0 = lis[r0], li1 = lis[r0+8];
        #pragma unroll
        for (int nb = 0; nb < 4; nb++) {
            int col = n*DH + wn*32 + nb*8 + 2*tig;
            size_t row0 = (size_t)(i0 + r0)*BATCH + b;
            size_t row1 = (size_t)(i0 + r0 + 8)*BATCH + b;
            *(float2*)&g_AV[row0*DM + col] = make_float2(oC[nb][0]*li0, oC[nb][1]*li0);
            *(float2*)&g_AV[row1*DM + col] = make_float2(oC[nb][2]*li1, oC[nb][3]*li1);
        }
    }
}

// LayerNorm over g_O rows -> d_out
__global__ __launch_bounds__(256)
void k_ln(const float* __restrict__ gamma, const float* __restrict__ beta,
          float* __restrict__ out)
{
    __shared__ float red[16];
    const int t = threadIdx.x;
    const size_t row = blockIdx.x;
    float4 x = *(const float4*)&g_O[row*DM + t*4];
    float s = x.x + x.y + x.z + x.w;
    float ss = x.x*x.x + x.y*x.y + x.z*x.z + x.w*x.w;
    #pragma unroll
    for (int m = 16; m > 0; m >>= 1) {
        s  += __shfl_xor_sync(0xffffffffu, s, m);
        ss += __shfl_xor_sync(0xffffffffu, ss, m);
    }
    if ((t&31) == 0) { red[t>>5] = s; red[8 + (t>>5)] = ss; }
    __syncthreads();
    if (t < 8) {
        float a = red[t], bsum = red[8+t];
        #pragma unroll
        for (int m = 4; m > 0; m >>= 1) {
            a    += __shfl_xor_sync(0xffu, a, m);
            bsum += __shfl_xor_sync(0xffu, bsum, m);
        }
        if (t == 0) { red[0] = a; red[8] = bsum; }
    }
    __syncthreads();
    float mu = red[0] * (1.f/DM);
    float var = red[8] * (1.f/DM) - mu*mu;
    float rs = rsqrtf(var + 1e-5f);
    float4 g = *(const float4*)&gamma[t*4];
    float4 be = *(const float4*)&beta[t*4];
    float4 y;
    y.x = (x.x-mu)*rs*g.x + be.x;
    y.y = (x.y-mu)*rs*g.y + be.y;
    y.z = (x.z-mu)*rs*g.z + be.z;
    y.w = (x.w-mu)*rs*g.w + be.w;
    *(float4*)&out[row*DM + t*4] = y;
}

extern "C" void kernel_launch(void* const* d_in, const int* in_sizes, int n_in,
                              void* d_out, int out_size)
{
    const float* content = (const float*)d_in[0];
    const float* rel_pos = (const float*)d_in[1];
    const float* mems    = (const float*)d_in[2];
    const float* rwb     = (const float*)d_in[3];
    const float* rrb     = (const float*)d_in[4];
    const float* Wqkv    = (const float*)d_in[5];
    const float* Wr      = (const float*)d_in[6];
    const float* Wo      = (const float*)d_in[7];
    const float* gamma   = (const float*)d_in[8];
    const float* beta    = (const float*)d_in[9];
    float* out = (float*)d_out;

    cudaFuncSetAttribute(k_attn,  cudaFuncAttributeMaxDynamicSharedMemorySize, SMEM_ATTN);
    cudaFuncSetAttribute(k_qkv,   cudaFuncAttributeMaxDynamicSharedMemorySize, SMEM_GEMM);
    cudaFuncSetAttribute(k_rproj, cudaFuncAttributeMaxDynamicSharedMemorySize, SMEM_GEMM);
    cudaFuncSetAttribute(k_out,   cudaFuncAttributeMaxDynamicSharedMemorySize, SMEM_GEMM);

    __nv_bfloat16 *Ah, *Al, *W3h, *W3l, *Rph, *Rpl, *Wrh, *Wrl, *Woh, *Wol, *AVh, *AVl;
    float *AV, *Kf, *Vf, *Rf;
    __half *Kh, *Vh, *Rh;
    cudaGetSymbolAddress((void**)&Ah,  g_Ah);
    cudaGetSymbolAddress((void**)&Al,  g_Al);
    cudaGetSymbolAddress((void**)&W3h, g_W3h);
    cudaGetSymbolAddress((void**)&W3l, g_W3l);
    cudaGetSymbolAddress((void**)&Rph, g_Rph);
    cudaGetSymbolAddress((void**)&Rpl, g_Rpl);
    cudaGetSymbolAddress((void**)&Wrh, g_Wrh);
    cudaGetSymbolAddress((void**)&Wrl, g_Wrl);
    cudaGetSymbolAddress((void**)&Woh, g_Woh);
    cudaGetSymbolAddress((void**)&Wol, g_Wol);
    cudaGetSymbolAddress((void**)&AVh, g_AVh);
    cudaGetSymbolAddress((void**)&AVl, g_AVl);
    cudaGetSymbolAddress((void**)&AV,  g_AV);
    cudaGetSymbolAddress((void**)&Kf,  g_K);
    cudaGetSymbolAddress((void**)&Vf,  g_V);
    cudaGetSymbolAddress((void**)&Rf,  g_R);
    cudaGetSymbolAddress((void**)&Kh,  g_Kh);
    cudaGetSymbolAddress((void**)&Vh,  g_Vh);
    cudaGetSymbolAddress((void**)&Rh,  g_Rh);

    const int MB = 4096*DM/4;
    k_splitb<<<(MB+255)/256, 256>>>(mems,    Ah,           Al,           MB);
    k_splitb<<<(MB+255)/256, 256>>>(content, Ah + 4096*DM, Al + 4096*DM, MB);
    k_splitb<<<(DM*3072/4+255)/256, 256>>>(Wqkv,    W3h, W3l, DM*3072/4);
    k_splitb<<<(KLENN*DM/4+255)/256, 256>>>(rel_pos, Rph, Rpl, KLENN*DM/4);
    k_splitb<<<(DM*DM/4+255)/256, 256>>>(Wr, Wrh, Wrl, DM*DM/4);
    k_splitb<<<(DM*DM/4+255)/256, 256>>>(Wo, Woh, Wol, DM*DM/4);

    k_qkv  <<<dim3(24, 64), 256, SMEM_GEMM>>>();
    k_rproj<<<dim3(8, 16),  256, SMEM_GEMM>>>();

    const int QN4 = BATCH*NH*QLEN*DH/4;
    const int KN4 = BATCH*NH*KLENN*DH/4;
    const int RN4 = NH*KLENN*DH/4;
    k_qprep <<<(QN4+255)/256, 256>>>(rwb, rrb);
    k_tohalf<<<(KN4+255)/256, 256>>>(Kf, Kh, KN4);
    k_tohalf<<<(KN4+255)/256, 256>>>(Vf, Vh, KN4);
    k_tohalf<<<(RN4+255)/256, 256>>>(Rf, Rh, RN4);

    k_attn <<<dim3(QLEN/64, NH, BATCH), 256, SMEM_ATTN>>>();

    k_splitb<<<(MB+255)/256, 256>>>(AV, AVh, AVl, MB);
    k_out  <<<dim3(8, 32),  256, SMEM_GEMM>>>(content);
    k_ln   <<<QLEN*BATCH, 256>>>(gamma, beta, out);
}